// round 2
// baseline (speedup 1.0000x reference)
#include <cuda_runtime.h>
#include <math.h>

#define T_TOK 2048
#define S_C   512
#define L_X   1536
#define DIM   1024
#define NH    16
#define HD    64
#define FFD   4096

// ---------------- static scratch (no allocations allowed) ----------------
__device__ float g_ln [T_TOK * DIM];
__device__ float g_qk [T_TOK * 2 * DIM];
__device__ float g_q  [T_TOK * DIM];
__device__ float g_k  [T_TOK * DIM];
__device__ float g_v  [T_TOK * DIM];
__device__ float g_y  [T_TOK * DIM];
__device__ float g_x1 [T_TOK * DIM];
__device__ float g_ln2[T_TOK * DIM];
__device__ float g_ff1[T_TOK * FFD];
__device__ float g_ff3[T_TOK * FFD];

// ---------------- LayerNorm over concat([c, x]) rows ----------------
__global__ void ln_concat(const float* __restrict__ x, const float* __restrict__ c,
                          float* __restrict__ out) {
    int row = blockIdx.x;
    const float* src = (row < S_C) ? (c + (size_t)row * DIM)
                                   : (x + (size_t)(row - S_C) * DIM);
    float* dst = out + (size_t)row * DIM;
    __shared__ float red[256];
    int tid = threadIdx.x;

    float4 v = ((const float4*)src)[tid];
    float s = v.x + v.y + v.z + v.w;
    red[tid] = s; __syncthreads();
    for (int o = 128; o > 0; o >>= 1) { if (tid < o) red[tid] += red[tid + o]; __syncthreads(); }
    float mean = red[0] * (1.0f / DIM);
    __syncthreads();

    float dx = v.x - mean, dy = v.y - mean, dz = v.z - mean, dw = v.w - mean;
    red[tid] = dx*dx + dy*dy + dz*dz + dw*dw; __syncthreads();
    for (int o = 128; o > 0; o >>= 1) { if (tid < o) red[tid] += red[tid + o]; __syncthreads(); }
    float inv = rsqrtf(red[0] * (1.0f / DIM) + 1e-6f);

    float4 o4 = make_float4(dx * inv, dy * inv, dz * inv, dw * inv);
    ((float4*)dst)[tid] = o4;
}

__global__ void ln_rows(const float* __restrict__ in, float* __restrict__ out) {
    int row = blockIdx.x;
    const float* src = in + (size_t)row * DIM;
    float* dst = out + (size_t)row * DIM;
    __shared__ float red[256];
    int tid = threadIdx.x;

    float4 v = ((const float4*)src)[tid];
    red[tid] = v.x + v.y + v.z + v.w; __syncthreads();
    for (int o = 128; o > 0; o >>= 1) { if (tid < o) red[tid] += red[tid + o]; __syncthreads(); }
    float mean = red[0] * (1.0f / DIM);
    __syncthreads();

    float dx = v.x - mean, dy = v.y - mean, dz = v.z - mean, dw = v.w - mean;
    red[tid] = dx*dx + dy*dy + dz*dz + dw*dw; __syncthreads();
    for (int o = 128; o > 0; o >>= 1) { if (tid < o) red[tid] += red[tid + o]; __syncthreads(); }
    float inv = rsqrtf(red[0] * (1.0f / DIM) + 1e-6f);

    ((float4*)dst)[tid] = make_float4(dx * inv, dy * inv, dz * inv, dw * inv);
}

// ---------------- tiled SGEMM: C[m][n] = A[m][:] . W[n][:] (+bias)(+res) ----------------
// A: [M,K] row-major with leading dim lda. W: [N,K] row-major (ld = K).
// grid.x = N/64, grid.y = M/64, block = 256. All dims multiples of tile sizes.
__global__ void sgemm_bias_res(const float* __restrict__ A, int lda,
                               const float* __restrict__ W,
                               const float* __restrict__ bias,
                               const float* __restrict__ res, int ldres,
                               float* __restrict__ C, int ldc, int K) {
    __shared__ float As[16][64];
    __shared__ float Bs[16][64];
    int tid = threadIdx.x;
    int tx = tid & 15, ty = tid >> 4;
    int m0 = blockIdx.y * 64, n0 = blockIdx.x * 64;

    int lrow  = tid >> 2;        // 0..63
    int lcol4 = (tid & 3) * 4;   // 0,4,8,12
    const float* Aptr = A + (size_t)(m0 + lrow) * lda + lcol4;
    const float* Wptr = W + (size_t)(n0 + lrow) * K   + lcol4;

    float acc[4][4] = {};

    for (int k0 = 0; k0 < K; k0 += 16) {
        float4 a = *(const float4*)(Aptr + k0);
        float4 b = *(const float4*)(Wptr + k0);
        As[lcol4 + 0][lrow] = a.x; As[lcol4 + 1][lrow] = a.y;
        As[lcol4 + 2][lrow] = a.z; As[lcol4 + 3][lrow] = a.w;
        Bs[lcol4 + 0][lrow] = b.x; Bs[lcol4 + 1][lrow] = b.y;
        Bs[lcol4 + 2][lrow] = b.z; Bs[lcol4 + 3][lrow] = b.w;
        __syncthreads();
        #pragma unroll
        for (int k = 0; k < 16; k++) {
            float4 av = *(const float4*)&As[k][ty * 4];
            float4 bv = *(const float4*)&Bs[k][tx * 4];
            float aa[4] = {av.x, av.y, av.z, av.w};
            float bb[4] = {bv.x, bv.y, bv.z, bv.w};
            #pragma unroll
            for (int i = 0; i < 4; i++)
                #pragma unroll
                for (int j = 0; j < 4; j++)
                    acc[i][j] = fmaf(aa[i], bb[j], acc[i][j]);
        }
        __syncthreads();
    }

    #pragma unroll
    for (int i = 0; i < 4; i++) {
        int m = m0 + ty * 4 + i;
        #pragma unroll
        for (int j = 0; j < 4; j++) {
            int n = n0 + tx * 4 + j;
            float vv = acc[i][j];
            if (bias) vv += bias[n];
            if (res)  vv += res[(size_t)m * ldres + n];
            C[(size_t)m * ldc + n] = vv;
        }
    }
}

// ---------------- per-head RMSNorm + RoPE on q,k ----------------
// qk: [T, 2*DIM]; q cols [0,1024), k cols [1024,2048). One warp per (t,h).
__global__ void rmsrope(const float* __restrict__ qk, const float* __restrict__ freqs,
                        const float* __restrict__ px_qn, const float* __restrict__ px_kn,
                        const float* __restrict__ pc_qn, const float* __restrict__ pc_kn,
                        float* __restrict__ q, float* __restrict__ k) {
    int t = blockIdx.x;
    int h = blockIdx.y * 4 + threadIdx.y;
    int lane = threadIdx.x;

    const float* qn = (t < S_C) ? pc_qn : px_qn;
    const float* kn = (t < S_C) ? pc_kn : px_kn;

    const float* src = qk + (size_t)t * (2 * DIM) + h * HD;
    float2 qv = *(const float2*)(src + lane * 2);
    float2 kv = *(const float2*)(src + DIM + lane * 2);

    float qs = qv.x * qv.x + qv.y * qv.y;
    float ks = kv.x * kv.x + kv.y * kv.y;
    #pragma unroll
    for (int o = 16; o > 0; o >>= 1) {
        qs += __shfl_xor_sync(0xFFFFFFFFu, qs, o);
        ks += __shfl_xor_sync(0xFFFFFFFFu, ks, o);
    }
    float qinv = rsqrtf(qs * (1.0f / HD) + 1e-6f);
    float kinv = rsqrtf(ks * (1.0f / HD) + 1e-6f);

    float cosv = freqs[((size_t)t * 32 + lane) * 2 + 0];
    float sinv = freqs[((size_t)t * 32 + lane) * 2 + 1];

    float q0 = qv.x * qinv * qn[lane * 2 + 0];
    float q1 = qv.y * qinv * qn[lane * 2 + 1];
    float k0 = kv.x * kinv * kn[lane * 2 + 0];
    float k1 = kv.y * kinv * kn[lane * 2 + 1];

    size_t base = (size_t)t * DIM + h * HD + lane * 2;
    q[base + 0] = q0 * cosv - q1 * sinv;
    q[base + 1] = q0 * sinv + q1 * cosv;
    k[base + 0] = k0 * cosv - k1 * sinv;
    k[base + 1] = k0 * sinv + k1 * cosv;
}

// ---------------- causal attention, one block per (query t, head h) ----------------
__global__ void attn_kernel(const float* __restrict__ q, const float* __restrict__ k,
                            const float* __restrict__ v, float* __restrict__ y) {
    int t = blockIdx.x, h = blockIdx.y, tid = threadIdx.x;
    __shared__ float sc[T_TOK];
    __shared__ float red[128];
    __shared__ float qs[HD];
    __shared__ float s_max, s_sum;

    if (tid < HD) qs[tid] = q[(size_t)t * DIM + h * HD + tid];
    __syncthreads();

    float lmax = -1e30f;
    for (int j = tid; j <= t; j += 128) {
        const float* kr = k + (size_t)j * DIM + h * HD;
        float s = 0.0f;
        #pragma unroll
        for (int d = 0; d < HD; d += 4) {
            float4 kk = *(const float4*)(kr + d);
            s += qs[d] * kk.x + qs[d + 1] * kk.y + qs[d + 2] * kk.z + qs[d + 3] * kk.w;
        }
        s *= 0.125f;   // 1/sqrt(64)
        sc[j] = s;
        lmax = fmaxf(lmax, s);
    }
    red[tid] = lmax; __syncthreads();
    for (int o = 64; o > 0; o >>= 1) { if (tid < o) red[tid] = fmaxf(red[tid], red[tid + o]); __syncthreads(); }
    if (tid == 0) s_max = red[0];
    __syncthreads();
    float m = s_max;

    float lsum = 0.0f;
    for (int j = tid; j <= t; j += 128) {
        float p = __expf(sc[j] - m);
        sc[j] = p;
        lsum += p;
    }
    red[tid] = lsum; __syncthreads();
    for (int o = 64; o > 0; o >>= 1) { if (tid < o) red[tid] += red[tid + o]; __syncthreads(); }
    if (tid == 0) s_sum = red[0];
    __syncthreads();
    float inv = 1.0f / s_sum;

    int d = tid & 63, part = tid >> 6;
    float acc = 0.0f;
    for (int j = part; j <= t; j += 2)
        acc += sc[j] * v[(size_t)j * DIM + h * HD + d];
    red[tid] = acc; __syncthreads();
    if (tid < 64)
        y[(size_t)t * DIM + h * HD + tid] = (red[tid] + red[tid + 64]) * inv;
}

// ---------------- SwiGLU gate: a = silu(a) * b ----------------
__global__ void silu_mul(float* __restrict__ a, const float* __restrict__ b, int n4) {
    int i = blockIdx.x * blockDim.x + threadIdx.x;
    if (i < n4) {
        float4 av = ((float4*)a)[i];
        float4 bv = ((const float4*)b)[i];
        av.x = av.x / (1.0f + __expf(-av.x)) * bv.x;
        av.y = av.y / (1.0f + __expf(-av.y)) * bv.y;
        av.z = av.z / (1.0f + __expf(-av.z)) * bv.z;
        av.w = av.w / (1.0f + __expf(-av.w)) * bv.w;
        ((float4*)a)[i] = av;
    }
}

// ---------------- launch ----------------
extern "C" void kernel_launch(void* const* d_in, const int* in_sizes, int n_in,
                              void* d_out, int out_size) {
    const float* x        = (const float*)d_in[0];
    const float* c        = (const float*)d_in[1];
    const float* freqs    = (const float*)d_in[2];
    const float* px_qk_w  = (const float*)d_in[3];
    const float* px_qn    = (const float*)d_in[4];
    const float* px_kn    = (const float*)d_in[5];
    const float* px_v_w   = (const float*)d_in[6];
    const float* px_v_b   = (const float*)d_in[7];
    const float* pc_qk_w  = (const float*)d_in[8];
    const float* pc_qn    = (const float*)d_in[9];
    const float* pc_kn    = (const float*)d_in[10];
    const float* pc_v_w   = (const float*)d_in[11];
    const float* pc_v_b   = (const float*)d_in[12];
    const float* p1_proj_w= (const float*)d_in[13];
    const float* p1_proj_b= (const float*)d_in[14];
    const float* p1_w1    = (const float*)d_in[15];
    const float* p1_b1    = (const float*)d_in[16];
    const float* p1_w3    = (const float*)d_in[17];
    const float* p1_b3    = (const float*)d_in[18];
    const float* p1_w2    = (const float*)d_in[19];
    const float* p1_b2    = (const float*)d_in[20];
    const float* p2_proj_w= (const float*)d_in[21];
    const float* p2_proj_b= (const float*)d_in[22];
    const float* p2_w1    = (const float*)d_in[23];
    const float* p2_b1    = (const float*)d_in[24];
    const float* p2_w3    = (const float*)d_in[25];
    const float* p2_b3    = (const float*)d_in[26];
    const float* p2_w2    = (const float*)d_in[27];
    const float* p2_b2    = (const float*)d_in[28];
    float* out = (float*)d_out;

    float *ln_, *qk_, *q_, *k_, *v_, *y_, *x1_, *ln2_, *ff1_, *ff3_;
    cudaGetSymbolAddress((void**)&ln_,  g_ln);
    cudaGetSymbolAddress((void**)&qk_,  g_qk);
    cudaGetSymbolAddress((void**)&q_,   g_q);
    cudaGetSymbolAddress((void**)&k_,   g_k);
    cudaGetSymbolAddress((void**)&v_,   g_v);
    cudaGetSymbolAddress((void**)&y_,   g_y);
    cudaGetSymbolAddress((void**)&x1_,  g_x1);
    cudaGetSymbolAddress((void**)&ln2_, g_ln2);
    cudaGetSymbolAddress((void**)&ff1_, g_ff1);
    cudaGetSymbolAddress((void**)&ff3_, g_ff3);

    // 1. LN on both streams into unified [c; x] token order
    ln_concat<<<T_TOK, 256>>>(x, c, ln_);

    // 2. qk projections (per-stream weights), write [T, 2048]
    sgemm_bias_res<<<dim3(2 * DIM / 64, S_C / 64), 256>>>(ln_, DIM, pc_qk_w, nullptr, nullptr, 0, qk_, 2 * DIM, DIM);
    sgemm_bias_res<<<dim3(2 * DIM / 64, L_X / 64), 256>>>(ln_ + (size_t)S_C * DIM, DIM, px_qk_w, nullptr, nullptr, 0, qk_ + (size_t)S_C * 2 * DIM, 2 * DIM, DIM);

    // 3. v projections (+bias)
    sgemm_bias_res<<<dim3(DIM / 64, S_C / 64), 256>>>(ln_, DIM, pc_v_w, pc_v_b, nullptr, 0, v_, DIM, DIM);
    sgemm_bias_res<<<dim3(DIM / 64, L_X / 64), 256>>>(ln_ + (size_t)S_C * DIM, DIM, px_v_w, px_v_b, nullptr, 0, v_ + (size_t)S_C * DIM, DIM, DIM);

    // 4. per-head RMSNorm + RoPE
    rmsrope<<<dim3(T_TOK, NH / 4), dim3(32, 4)>>>(qk_, freqs, px_qn, px_kn, pc_qn, pc_kn, q_, k_);

    // 5. causal attention
    attn_kernel<<<dim3(T_TOK, NH), 128>>>(q_, k_, v_, y_);

    // 6. output projection + residual (per stream): x1 = resid + y @ pw^T + pb
    sgemm_bias_res<<<dim3(DIM / 64, S_C / 64), 256>>>(y_, DIM, p2_proj_w, p2_proj_b, c, DIM, x1_, DIM, DIM);
    sgemm_bias_res<<<dim3(DIM / 64, L_X / 64), 256>>>(y_ + (size_t)S_C * DIM, DIM, p1_proj_w, p1_proj_b, x, DIM, x1_ + (size_t)S_C * DIM, DIM, DIM);

    // 7. second LN
    ln_rows<<<T_TOK, 256>>>(x1_, ln2_);

    // 8. MLP up projections
    sgemm_bias_res<<<dim3(FFD / 64, S_C / 64), 256>>>(ln2_, DIM, p2_w1, p2_b1, nullptr, 0, ff1_, FFD, DIM);
    sgemm_bias_res<<<dim3(FFD / 64, S_C / 64), 256>>>(ln2_, DIM, p2_w3, p2_b3, nullptr, 0, ff3_, FFD, DIM);
    sgemm_bias_res<<<dim3(FFD / 64, L_X / 64), 256>>>(ln2_ + (size_t)S_C * DIM, DIM, p1_w1, p1_b1, nullptr, 0, ff1_ + (size_t)S_C * FFD, FFD, DIM);
    sgemm_bias_res<<<dim3(FFD / 64, L_X / 64), 256>>>(ln2_ + (size_t)S_C * DIM, DIM, p1_w3, p1_b3, nullptr, 0, ff3_ + (size_t)S_C * FFD, FFD, DIM);

    // 9. SwiGLU gate
    {
        int n4 = T_TOK * FFD / 4;
        silu_mul<<<(n4 + 255) / 256, 256>>>(ff1_, ff3_, n4);
    }

    // 10. MLP down projection + residual -> final outputs (x_out first, then c_out)
    sgemm_bias_res<<<dim3(DIM / 64, S_C / 64), 256>>>(ff1_, FFD, p2_w2, p2_b2, x1_, DIM, out + (size_t)L_X * DIM, DIM, FFD);
    sgemm_bias_res<<<dim3(DIM / 64, L_X / 64), 256>>>(ff1_ + (size_t)S_C * FFD, FFD, p1_w2, p1_b2, x1_ + (size_t)S_C * DIM, DIM, out, DIM, FFD);
}

// round 4
// speedup vs baseline: 3.1042x; 3.1042x over previous
#include <cuda_runtime.h>
#include <cstdint>
#include <math.h>

#define T_TOK 2048
#define S_C   512
#define L_X   1536
#define DIM   1024
#define NH    16
#define HD    64
#define FFD   4096

// ---------------- static scratch (no allocations allowed) ----------------
__device__ float g_ln [T_TOK * DIM];
__device__ float g_qk [T_TOK * 2 * DIM];
__device__ float g_q  [T_TOK * DIM];
__device__ float g_k  [T_TOK * DIM];
__device__ float g_v  [T_TOK * DIM];
__device__ float g_y  [T_TOK * DIM];
__device__ float g_x1 [T_TOK * DIM];
__device__ float g_ln2[T_TOK * DIM];
__device__ float g_ff1[T_TOK * FFD];
__device__ float g_ff3[T_TOK * FFD];

// ---------------- small helpers ----------------
__device__ __forceinline__ uint32_t f2tf(float x) {
    uint32_t r;
    asm("cvt.rna.tf32.f32 %0, %1;" : "=r"(r) : "f"(x));
    return r;
}

__device__ __forceinline__ void mma_tf32(float* c, const uint32_t* a, const uint32_t* b) {
    asm volatile(
        "mma.sync.aligned.m16n8k8.row.col.f32.tf32.tf32.f32 "
        "{%0,%1,%2,%3}, {%4,%5,%6,%7}, {%8,%9}, {%0,%1,%2,%3};\n"
        : "+f"(c[0]), "+f"(c[1]), "+f"(c[2]), "+f"(c[3])
        : "r"(a[0]), "r"(a[1]), "r"(a[2]), "r"(a[3]), "r"(b[0]), "r"(b[1]));
}

__device__ __forceinline__ void cp16(void* s, const void* g) {
    uint32_t sa = (uint32_t)__cvta_generic_to_shared(s);
    asm volatile("cp.async.cg.shared.global [%0], [%1], 16;\n" :: "r"(sa), "l"(g));
}

// ---------------- LayerNorm over concat([c, x]) rows ----------------
__global__ void ln_concat(const float* __restrict__ x, const float* __restrict__ c,
                          float* __restrict__ out) {
    int row = blockIdx.x;
    const float* src = (row < S_C) ? (c + (size_t)row * DIM)
                                   : (x + (size_t)(row - S_C) * DIM);
    float* dst = out + (size_t)row * DIM;
    __shared__ float red[256];
    int tid = threadIdx.x;

    float4 v = ((const float4*)src)[tid];
    red[tid] = v.x + v.y + v.z + v.w; __syncthreads();
    for (int o = 128; o > 0; o >>= 1) { if (tid < o) red[tid] += red[tid + o]; __syncthreads(); }
    float mean = red[0] * (1.0f / DIM);
    __syncthreads();

    float dx = v.x - mean, dy = v.y - mean, dz = v.z - mean, dw = v.w - mean;
    red[tid] = dx*dx + dy*dy + dz*dz + dw*dw; __syncthreads();
    for (int o = 128; o > 0; o >>= 1) { if (tid < o) red[tid] += red[tid + o]; __syncthreads(); }
    float inv = rsqrtf(red[0] * (1.0f / DIM) + 1e-6f);

    ((float4*)dst)[tid] = make_float4(dx * inv, dy * inv, dz * inv, dw * inv);
}

__global__ void ln_rows(const float* __restrict__ in, float* __restrict__ out) {
    int row = blockIdx.x;
    const float* src = in + (size_t)row * DIM;
    float* dst = out + (size_t)row * DIM;
    __shared__ float red[256];
    int tid = threadIdx.x;

    float4 v = ((const float4*)src)[tid];
    red[tid] = v.x + v.y + v.z + v.w; __syncthreads();
    for (int o = 128; o > 0; o >>= 1) { if (tid < o) red[tid] += red[tid + o]; __syncthreads(); }
    float mean = red[0] * (1.0f / DIM);
    __syncthreads();

    float dx = v.x - mean, dy = v.y - mean, dz = v.z - mean, dw = v.w - mean;
    red[tid] = dx*dx + dy*dy + dz*dz + dw*dw; __syncthreads();
    for (int o = 128; o > 0; o >>= 1) { if (tid < o) red[tid] += red[tid + o]; __syncthreads(); }
    float inv = rsqrtf(red[0] * (1.0f / DIM) + 1e-6f);

    ((float4*)dst)[tid] = make_float4(dx * inv, dy * inv, dz * inv, dw * inv);
}

// ---------------- tf32 tensor-core GEMM: C = A . W^T (+bias)(+res) ----------------
// A: [M,K] row-major (leading dim lda). W: [N,K] row-major (ld = K).
// BM=BN=128, BK=32. 256 threads = 8 warps, warp tile 64x32 (m x n).
// grid = (N/128, M/128). All dims multiples of tile sizes. Dynamic smem 73728B.
__global__ void __launch_bounds__(256) gemm_tf32(
        const float* __restrict__ A, int lda,
        const float* __restrict__ W,
        const float* __restrict__ bias,
        const float* __restrict__ res, int ldres,
        float* __restrict__ C, int ldc, int K) {
    extern __shared__ float sm[];
    const int ASZ = 128 * 36;
    float* bufA[2] = { sm,            sm + 2 * ASZ };
    float* bufB[2] = { sm + ASZ,      sm + 3 * ASZ };

    int tid = threadIdx.x;
    int m0 = blockIdx.y * 128, n0 = blockIdx.x * 128;
    int wid = tid >> 5, lane = tid & 31;
    int wm = (wid >> 2) * 64;   // 0 or 64
    int wn = (wid & 3) * 32;    // 0,32,64,96
    int lr = lane >> 2;         // 0..7
    int lc = lane & 3;          // 0..3

    float acc[4][4][4];
    #pragma unroll
    for (int i = 0; i < 4; i++)
        #pragma unroll
        for (int j = 0; j < 4; j++)
            #pragma unroll
            for (int r = 0; r < 4; r++) acc[i][j][r] = 0.0f;

    int KT = K / 32;

    // prefetch tile 0
    {
        #pragma unroll
        for (int i = 0; i < 4; i++) {
            int f = tid + i * 256;
            int row = f >> 3, c4 = (f & 7) * 4;
            cp16(bufA[0] + row * 36 + c4, A + (size_t)(m0 + row) * lda + c4);
            cp16(bufB[0] + row * 36 + c4, W + (size_t)(n0 + row) * K + c4);
        }
        asm volatile("cp.async.commit_group;\n");
    }

    for (int kt = 0; kt < KT; kt++) {
        if (kt + 1 < KT) {
            int k0 = (kt + 1) * 32;
            int b = (kt + 1) & 1;
            #pragma unroll
            for (int i = 0; i < 4; i++) {
                int f = tid + i * 256;
                int row = f >> 3, c4 = (f & 7) * 4;
                cp16(bufA[b] + row * 36 + c4, A + (size_t)(m0 + row) * lda + k0 + c4);
                cp16(bufB[b] + row * 36 + c4, W + (size_t)(n0 + row) * K + k0 + c4);
            }
            asm volatile("cp.async.commit_group;\n");
            asm volatile("cp.async.wait_group 1;\n");
        } else {
            asm volatile("cp.async.wait_group 0;\n");
        }
        __syncthreads();

        const float* As = bufA[kt & 1];
        const float* Bs = bufB[kt & 1];
        #pragma unroll
        for (int k8 = 0; k8 < 32; k8 += 8) {
            uint32_t af[4][4], bf[4][2];
            #pragma unroll
            for (int mt = 0; mt < 4; mt++) {
                int mb = wm + mt * 16;
                af[mt][0] = f2tf(As[(mb + lr)     * 36 + k8 + lc]);
                af[mt][1] = f2tf(As[(mb + lr + 8) * 36 + k8 + lc]);
                af[mt][2] = f2tf(As[(mb + lr)     * 36 + k8 + lc + 4]);
                af[mt][3] = f2tf(As[(mb + lr + 8) * 36 + k8 + lc + 4]);
            }
            #pragma unroll
            for (int nt = 0; nt < 4; nt++) {
                int nb = wn + nt * 8;
                bf[nt][0] = f2tf(Bs[(nb + lr) * 36 + k8 + lc]);
                bf[nt][1] = f2tf(Bs[(nb + lr) * 36 + k8 + lc + 4]);
            }
            #pragma unroll
            for (int mt = 0; mt < 4; mt++)
                #pragma unroll
                for (int nt = 0; nt < 4; nt++)
                    mma_tf32(acc[mt][nt], af[mt], bf[nt]);
        }
        __syncthreads();
    }

    // epilogue
    #pragma unroll
    for (int mt = 0; mt < 4; mt++) {
        #pragma unroll
        for (int nt = 0; nt < 4; nt++) {
            int n = n0 + wn + nt * 8 + lc * 2;
            float b0 = 0.0f, b1 = 0.0f;
            if (bias) { b0 = bias[n]; b1 = bias[n + 1]; }
            #pragma unroll
            for (int half = 0; half < 2; half++) {
                int m = m0 + wm + mt * 16 + lr + half * 8;
                float v0 = acc[mt][nt][half * 2 + 0] + b0;
                float v1 = acc[mt][nt][half * 2 + 1] + b1;
                if (res) {
                    v0 += res[(size_t)m * ldres + n];
                    v1 += res[(size_t)m * ldres + n + 1];
                }
                C[(size_t)m * ldc + n]     = v0;
                C[(size_t)m * ldc + n + 1] = v1;
            }
        }
    }
}

// ---------------- per-head RMSNorm + RoPE on q,k ----------------
__global__ void rmsrope(const float* __restrict__ qk, const float* __restrict__ freqs,
                        const float* __restrict__ px_qn, const float* __restrict__ px_kn,
                        const float* __restrict__ pc_qn, const float* __restrict__ pc_kn,
                        float* __restrict__ q, float* __restrict__ k) {
    int t = blockIdx.x;
    int h = blockIdx.y * 4 + threadIdx.y;
    int lane = threadIdx.x;

    const float* qn = (t < S_C) ? pc_qn : px_qn;
    const float* kn = (t < S_C) ? pc_kn : px_kn;

    const float* src = qk + (size_t)t * (2 * DIM) + h * HD;
    float2 qv = *(const float2*)(src + lane * 2);
    float2 kv = *(const float2*)(src + DIM + lane * 2);

    float qs = qv.x * qv.x + qv.y * qv.y;
    float ks = kv.x * kv.x + kv.y * kv.y;
    #pragma unroll
    for (int o = 16; o > 0; o >>= 1) {
        qs += __shfl_xor_sync(0xFFFFFFFFu, qs, o);
        ks += __shfl_xor_sync(0xFFFFFFFFu, ks, o);
    }
    float qinv = rsqrtf(qs * (1.0f / HD) + 1e-6f);
    float kinv = rsqrtf(ks * (1.0f / HD) + 1e-6f);

    float cosv = freqs[((size_t)t * 32 + lane) * 2 + 0];
    float sinv = freqs[((size_t)t * 32 + lane) * 2 + 1];

    float q0 = qv.x * qinv * qn[lane * 2 + 0];
    float q1 = qv.y * qinv * qn[lane * 2 + 1];
    float k0 = kv.x * kinv * kn[lane * 2 + 0];
    float k1 = kv.y * kinv * kn[lane * 2 + 1];

    size_t base = (size_t)t * DIM + h * HD + lane * 2;
    q[base + 0] = q0 * cosv - q1 * sinv;
    q[base + 1] = q0 * sinv + q1 * cosv;
    k[base + 0] = k0 * cosv - k1 * sinv;
    k[base + 1] = k0 * sinv + k1 * cosv;
}

// ---------------- tiled causal attention (flash-style) ----------------
// block = (q-tile of 64, head); 256 threads; online softmax; dynamic smem.
// QPAD must keep float4 rows 16B-aligned: 68 = 4-multiple (272B row stride).
#define QPAD 68
__global__ void __launch_bounds__(256) attn_tiled(
        const float* __restrict__ q, const float* __restrict__ k,
        const float* __restrict__ v, float* __restrict__ y) {
    extern __shared__ float sm[];
    float* QsT = sm;                    // [d][q] transposed
    float* KsT = sm + 64 * QPAD;        // [d][j]
    float* PsT = sm + 2 * 64 * QPAD;    // [j][q]
    float* Vs  = sm + 3 * 64 * QPAD;    // [j][d] natural

    int h = blockIdx.y;
    int qt = blockIdx.x;
    int q0 = qt * 64;
    int tid = threadIdx.x;
    int tx = tid & 15, ty = tid >> 4;

    // load Q tile transposed
    #pragma unroll
    for (int i = 0; i < 4; i++) {
        int f = tid + i * 256;
        int r = f >> 4, d4 = (f & 15) * 4;
        float4 val = *(const float4*)(q + (size_t)(q0 + r) * DIM + h * HD + d4);
        QsT[(d4 + 0) * QPAD + r] = val.x;
        QsT[(d4 + 1) * QPAD + r] = val.y;
        QsT[(d4 + 2) * QPAD + r] = val.z;
        QsT[(d4 + 3) * QPAD + r] = val.w;
    }

    float m_[4], l_[4], o[4][4];
    #pragma unroll
    for (int i = 0; i < 4; i++) {
        m_[i] = -1e30f; l_[i] = 0.0f;
        #pragma unroll
        for (int j = 0; j < 4; j++) o[i][j] = 0.0f;
    }

    for (int kt = 0; kt <= qt; kt++) {
        int j0 = kt * 64;
        __syncthreads();   // previous PV done before overwrite of K/V
        #pragma unroll
        for (int i = 0; i < 4; i++) {
            int f = tid + i * 256;
            int r = f >> 4, d4 = (f & 15) * 4;
            float4 kk = *(const float4*)(k + (size_t)(j0 + r) * DIM + h * HD + d4);
            KsT[(d4 + 0) * QPAD + r] = kk.x;
            KsT[(d4 + 1) * QPAD + r] = kk.y;
            KsT[(d4 + 2) * QPAD + r] = kk.z;
            KsT[(d4 + 3) * QPAD + r] = kk.w;
            float4 vv = *(const float4*)(v + (size_t)(j0 + r) * DIM + h * HD + d4);
            *(float4*)(Vs + r * 64 + d4) = vv;
        }
        __syncthreads();

        // S = Q K^T (64x64), thread microtile 4x4
        float s[4][4] = {};
        #pragma unroll 8
        for (int d = 0; d < 64; d++) {
            float4 a = *(const float4*)(QsT + d * QPAD + ty * 4);
            float4 b = *(const float4*)(KsT + d * QPAD + tx * 4);
            float aa[4] = {a.x, a.y, a.z, a.w};
            float bb[4] = {b.x, b.y, b.z, b.w};
            #pragma unroll
            for (int i = 0; i < 4; i++)
                #pragma unroll
                for (int jj = 0; jj < 4; jj++)
                    s[i][jj] = fmaf(aa[i], bb[jj], s[i][jj]);
        }

        bool diag = (kt == qt);
        #pragma unroll
        for (int i = 0; i < 4; i++)
            #pragma unroll
            for (int jj = 0; jj < 4; jj++) {
                float sv = s[i][jj] * 0.125f;
                if (diag && (tx * 4 + jj) > (ty * 4 + i)) sv = -1e30f;
                s[i][jj] = sv;
            }

        // online softmax per row (rows ty*4+i; 16 tx-lanes per row)
        #pragma unroll
        for (int i = 0; i < 4; i++) {
            float mx = fmaxf(fmaxf(s[i][0], s[i][1]), fmaxf(s[i][2], s[i][3]));
            #pragma unroll
            for (int off = 8; off > 0; off >>= 1)
                mx = fmaxf(mx, __shfl_xor_sync(0xFFFFFFFFu, mx, off));
            float nm = fmaxf(m_[i], mx);
            float f_ = __expf(m_[i] - nm);
            float rs = 0.0f;
            #pragma unroll
            for (int jj = 0; jj < 4; jj++) {
                float p = __expf(s[i][jj] - nm);
                s[i][jj] = p;
                rs += p;
            }
            #pragma unroll
            for (int off = 8; off > 0; off >>= 1)
                rs += __shfl_xor_sync(0xFFFFFFFFu, rs, off);
            l_[i] = l_[i] * f_ + rs;
            m_[i] = nm;
            #pragma unroll
            for (int jj = 0; jj < 4; jj++) o[i][jj] *= f_;
            #pragma unroll
            for (int jj = 0; jj < 4; jj++)
                PsT[(tx * 4 + jj) * QPAD + ty * 4 + i] = s[i][jj];
        }
        __syncthreads();

        // O += P V
        #pragma unroll 8
        for (int j = 0; j < 64; j++) {
            float4 a = *(const float4*)(PsT + j * QPAD + ty * 4);
            float4 b = *(const float4*)(Vs + j * 64 + tx * 4);
            float aa[4] = {a.x, a.y, a.z, a.w};
            float bb[4] = {b.x, b.y, b.z, b.w};
            #pragma unroll
            for (int i = 0; i < 4; i++)
                #pragma unroll
                for (int jj = 0; jj < 4; jj++)
                    o[i][jj] = fmaf(aa[i], bb[jj], o[i][jj]);
        }
    }

    #pragma unroll
    for (int i = 0; i < 4; i++) {
        float inv = 1.0f / l_[i];
        #pragma unroll
        for (int jj = 0; jj < 4; jj++)
            y[(size_t)(q0 + ty * 4 + i) * DIM + h * HD + tx * 4 + jj] = o[i][jj] * inv;
    }
}

// ---------------- SwiGLU gate: a = silu(a) * b ----------------
__global__ void silu_mul(float* __restrict__ a, const float* __restrict__ b, int n4) {
    int i = blockIdx.x * blockDim.x + threadIdx.x;
    if (i < n4) {
        float4 av = ((float4*)a)[i];
        float4 bv = ((const float4*)b)[i];
        av.x = av.x / (1.0f + __expf(-av.x)) * bv.x;
        av.y = av.y / (1.0f + __expf(-av.y)) * bv.y;
        av.z = av.z / (1.0f + __expf(-av.z)) * bv.z;
        av.w = av.w / (1.0f + __expf(-av.w)) * bv.w;
        ((float4*)a)[i] = av;
    }
}

// ---------------- launch ----------------
#define GEMM_SMEM (4 * 128 * 36 * 4)                 // 73728 B
#define ATTN_SMEM ((3 * 64 * QPAD + 64 * 64) * 4)    // 68608 B

extern "C" void kernel_launch(void* const* d_in, const int* in_sizes, int n_in,
                              void* d_out, int out_size) {
    const float* x        = (const float*)d_in[0];
    const float* c        = (const float*)d_in[1];
    const float* freqs    = (const float*)d_in[2];
    const float* px_qk_w  = (const float*)d_in[3];
    const float* px_qn    = (const float*)d_in[4];
    const float* px_kn    = (const float*)d_in[5];
    const float* px_v_w   = (const float*)d_in[6];
    const float* px_v_b   = (const float*)d_in[7];
    const float* pc_qk_w  = (const float*)d_in[8];
    const float* pc_qn    = (const float*)d_in[9];
    const float* pc_kn    = (const float*)d_in[10];
    const float* pc_v_w   = (const float*)d_in[11];
    const float* pc_v_b   = (const float*)d_in[12];
    const float* p1_proj_w= (const float*)d_in[13];
    const float* p1_proj_b= (const float*)d_in[14];
    const float* p1_w1    = (const float*)d_in[15];
    const float* p1_b1    = (const float*)d_in[16];
    const float* p1_w3    = (const float*)d_in[17];
    const float* p1_b3    = (const float*)d_in[18];
    const float* p1_w2    = (const float*)d_in[19];
    const float* p1_b2    = (const float*)d_in[20];
    const float* p2_proj_w= (const float*)d_in[21];
    const float* p2_proj_b= (const float*)d_in[22];
    const float* p2_w1    = (const float*)d_in[23];
    const float* p2_b1    = (const float*)d_in[24];
    const float* p2_w3    = (const float*)d_in[25];
    const float* p2_b3    = (const float*)d_in[26];
    const float* p2_w2    = (const float*)d_in[27];
    const float* p2_b2    = (const float*)d_in[28];
    float* out = (float*)d_out;

    float *ln_, *qk_, *q_, *k_, *v_, *y_, *x1_, *ln2_, *ff1_, *ff3_;
    cudaGetSymbolAddress((void**)&ln_,  g_ln);
    cudaGetSymbolAddress((void**)&qk_,  g_qk);
    cudaGetSymbolAddress((void**)&q_,   g_q);
    cudaGetSymbolAddress((void**)&k_,   g_k);
    cudaGetSymbolAddress((void**)&v_,   g_v);
    cudaGetSymbolAddress((void**)&y_,   g_y);
    cudaGetSymbolAddress((void**)&x1_,  g_x1);
    cudaGetSymbolAddress((void**)&ln2_, g_ln2);
    cudaGetSymbolAddress((void**)&ff1_, g_ff1);
    cudaGetSymbolAddress((void**)&ff3_, g_ff3);

    cudaFuncSetAttribute(gemm_tf32, cudaFuncAttributeMaxDynamicSharedMemorySize, GEMM_SMEM);
    cudaFuncSetAttribute(attn_tiled, cudaFuncAttributeMaxDynamicSharedMemorySize, ATTN_SMEM);

    // 1. LN on both streams into unified [c; x] token order
    ln_concat<<<T_TOK, 256>>>(x, c, ln_);

    // 2. qk projections (per-stream weights), write [T, 2048]
    gemm_tf32<<<dim3(2 * DIM / 128, S_C / 128), 256, GEMM_SMEM>>>(ln_, DIM, pc_qk_w, nullptr, nullptr, 0, qk_, 2 * DIM, DIM);
    gemm_tf32<<<dim3(2 * DIM / 128, L_X / 128), 256, GEMM_SMEM>>>(ln_ + (size_t)S_C * DIM, DIM, px_qk_w, nullptr, nullptr, 0, qk_ + (size_t)S_C * 2 * DIM, 2 * DIM, DIM);

    // 3. v projections (+bias)
    gemm_tf32<<<dim3(DIM / 128, S_C / 128), 256, GEMM_SMEM>>>(ln_, DIM, pc_v_w, pc_v_b, nullptr, 0, v_, DIM, DIM);
    gemm_tf32<<<dim3(DIM / 128, L_X / 128), 256, GEMM_SMEM>>>(ln_ + (size_t)S_C * DIM, DIM, px_v_w, px_v_b, nullptr, 0, v_ + (size_t)S_C * DIM, DIM, DIM);

    // 4. per-head RMSNorm + RoPE
    rmsrope<<<dim3(T_TOK, NH / 4), dim3(32, 4)>>>(qk_, freqs, px_qn, px_kn, pc_qn, pc_kn, q_, k_);

    // 5. tiled causal attention
    attn_tiled<<<dim3(T_TOK / 64, NH), 256, ATTN_SMEM>>>(q_, k_, v_, y_);

    // 6. output projection + residual (per stream)
    gemm_tf32<<<dim3(DIM / 128, S_C / 128), 256, GEMM_SMEM>>>(y_, DIM, p2_proj_w, p2_proj_b, c, DIM, x1_, DIM, DIM);
    gemm_tf32<<<dim3(DIM / 128, L_X / 128), 256, GEMM_SMEM>>>(y_ + (size_t)S_C * DIM, DIM, p1_proj_w, p1_proj_b, x, DIM, x1_ + (size_t)S_C * DIM, DIM, DIM);

    // 7. second LN
    ln_rows<<<T_TOK, 256>>>(x1_, ln2_);

    // 8. MLP up projections
    gemm_tf32<<<dim3(FFD / 128, S_C / 128), 256, GEMM_SMEM>>>(ln2_, DIM, p2_w1, p2_b1, nullptr, 0, ff1_, FFD, DIM);
    gemm_tf32<<<dim3(FFD / 128, S_C / 128), 256, GEMM_SMEM>>>(ln2_, DIM, p2_w3, p2_b3, nullptr, 0, ff3_, FFD, DIM);
    gemm_tf32<<<dim3(FFD / 128, L_X / 128), 256, GEMM_SMEM>>>(ln2_ + (size_t)S_C * DIM, DIM, p1_w1, p1_b1, nullptr, 0, ff1_ + (size_t)S_C * FFD, FFD, DIM);
    gemm_tf32<<<dim3(FFD / 128, L_X / 128), 256, GEMM_SMEM>>>(ln2_ + (size_t)S_C * DIM, DIM, p1_w3, p1_b3, nullptr, 0, ff3_ + (size_t)S_C * FFD, FFD, DIM);

    // 9. SwiGLU gate
    {
        int n4 = T_TOK * FFD / 4;
        silu_mul<<<(n4 + 255) / 256, 256>>>(ff1_, ff3_, n4);
    }

    // 10. MLP down projection + residual -> final outputs (x_out first, then c_out)
    gemm_tf32<<<dim3(DIM / 128, S_C / 128), 256, GEMM_SMEM>>>(ff1_, FFD, p2_w2, p2_b2, x1_, DIM, out + (size_t)L_X * DIM, DIM, FFD);
    gemm_tf32<<<dim3(DIM / 128, L_X / 128), 256, GEMM_SMEM>>>(ff1_ + (size_t)S_C * FFD, FFD, p1_w2, p1_b2, x1_ + (size_t)S_C * DIM, DIM, out, DIM, FFD);
}

// round 5
// speedup vs baseline: 4.3063x; 1.3872x over previous
#include <cuda_runtime.h>
#include <cstdint>
#include <math.h>

#define T_TOK 2048
#define S_C   512
#define L_X   1536
#define DIM   1024
#define NH    16
#define HD    64
#define FFD   4096

// ---------------- static scratch (no allocations allowed) ----------------
__device__ float g_ln [T_TOK * DIM];
__device__ float g_qk [T_TOK * 2 * DIM];
__device__ float g_q  [T_TOK * DIM];
__device__ float g_k  [T_TOK * DIM];
__device__ float g_v  [T_TOK * DIM];
__device__ float g_y  [T_TOK * DIM];
__device__ float g_x1 [T_TOK * DIM];
__device__ float g_ln2[T_TOK * DIM];
__device__ float g_ff1[T_TOK * FFD];
__device__ float g_ff3[T_TOK * FFD];

// ---------------- small helpers ----------------
__device__ __forceinline__ uint32_t f2tf(float x) {
    uint32_t r;
    asm("cvt.rna.tf32.f32 %0, %1;" : "=r"(r) : "f"(x));
    return r;
}

__device__ __forceinline__ void mma_tf32(float* c, const uint32_t* a, const uint32_t* b) {
    asm volatile(
        "mma.sync.aligned.m16n8k8.row.col.f32.tf32.tf32.f32 "
        "{%0,%1,%2,%3}, {%4,%5,%6,%7}, {%8,%9}, {%0,%1,%2,%3};\n"
        : "+f"(c[0]), "+f"(c[1]), "+f"(c[2]), "+f"(c[3])
        : "r"(a[0]), "r"(a[1]), "r"(a[2]), "r"(a[3]), "r"(b[0]), "r"(b[1]));
}

__device__ __forceinline__ void cp16(void* s, const void* g) {
    uint32_t sa = (uint32_t)__cvta_generic_to_shared(s);
    asm volatile("cp.async.cg.shared.global [%0], [%1], 16;\n" :: "r"(sa), "l"(g));
}

// Per-stream GEMM region: m-tiles [0, SPLIT) use r0 (c-stream), rest r1 (x-stream).
struct Region {
    const float* W;     // [N, K] row-major
    const float* bias;  // [N] or null
    const float* res;   // residual base, region-local rows, or null
    float* C;           // output base, region-local rows
};

// ---------------- LayerNorm over concat([c, x]) rows ----------------
__global__ void ln_concat(const float* __restrict__ x, const float* __restrict__ c,
                          float* __restrict__ out) {
    int row = blockIdx.x;
    const float* src = (row < S_C) ? (c + (size_t)row * DIM)
                                   : (x + (size_t)(row - S_C) * DIM);
    float* dst = out + (size_t)row * DIM;
    __shared__ float red[256];
    int tid = threadIdx.x;

    float4 v = ((const float4*)src)[tid];
    red[tid] = v.x + v.y + v.z + v.w; __syncthreads();
    for (int o = 128; o > 0; o >>= 1) { if (tid < o) red[tid] += red[tid + o]; __syncthreads(); }
    float mean = red[0] * (1.0f / DIM);
    __syncthreads();

    float dx = v.x - mean, dy = v.y - mean, dz = v.z - mean, dw = v.w - mean;
    red[tid] = dx*dx + dy*dy + dz*dz + dw*dw; __syncthreads();
    for (int o = 128; o > 0; o >>= 1) { if (tid < o) red[tid] += red[tid + o]; __syncthreads(); }
    float inv = rsqrtf(red[0] * (1.0f / DIM) + 1e-6f);

    ((float4*)dst)[tid] = make_float4(dx * inv, dy * inv, dz * inv, dw * inv);
}

__global__ void ln_rows(const float* __restrict__ in, float* __restrict__ out) {
    int row = blockIdx.x;
    const float* src = in + (size_t)row * DIM;
    float* dst = out + (size_t)row * DIM;
    __shared__ float red[256];
    int tid = threadIdx.x;

    float4 v = ((const float4*)src)[tid];
    red[tid] = v.x + v.y + v.z + v.w; __syncthreads();
    for (int o = 128; o > 0; o >>= 1) { if (tid < o) red[tid] += red[tid + o]; __syncthreads(); }
    float mean = red[0] * (1.0f / DIM);
    __syncthreads();

    float dx = v.x - mean, dy = v.y - mean, dz = v.z - mean, dw = v.w - mean;
    red[tid] = dx*dx + dy*dy + dz*dz + dw*dw; __syncthreads();
    for (int o = 128; o > 0; o >>= 1) { if (tid < o) red[tid] += red[tid + o]; __syncthreads(); }
    float inv = rsqrtf(red[0] * (1.0f / DIM) + 1e-6f);

    ((float4*)dst)[tid] = make_float4(dx * inv, dy * inv, dz * inv, dw * inv);
}

// ---------------- tf32 tensor-core GEMM, region-fused over full token range ----
// A: [2048, K] row-major contiguous (global rows). m-tile < SPLIT_MT -> region r0,
// else r1; res/C addressed by region-local row. BM=BN=128, BK=32, 256 thr = 8 warps.
#define SPLIT_MT (S_C / 128)
__global__ void __launch_bounds__(256, 2) gemm_tf32(
        const float* __restrict__ A, int lda,
        Region r0, Region r1,
        int ldres, int ldc, int K) {
    extern __shared__ float sm[];
    const int ASZ = 128 * 36;
    float* bufA[2] = { sm,            sm + 2 * ASZ };
    float* bufB[2] = { sm + ASZ,      sm + 3 * ASZ };

    int tid = threadIdx.x;
    int mt0 = blockIdx.y;
    int m0 = mt0 * 128, n0 = blockIdx.x * 128;
    bool is_c = (mt0 < SPLIT_MT);
    const Region& rg = is_c ? r0 : r1;
    int mloc0 = m0 - (is_c ? 0 : SPLIT_MT * 128);   // region-local row base

    int wid = tid >> 5, lane = tid & 31;
    int wm = (wid >> 2) * 64;   // 0 or 64
    int wn = (wid & 3) * 32;    // 0,32,64,96
    int lr = lane >> 2;         // 0..7
    int lc = lane & 3;          // 0..3

    float acc[4][4][4];
    #pragma unroll
    for (int i = 0; i < 4; i++)
        #pragma unroll
        for (int j = 0; j < 4; j++)
            #pragma unroll
            for (int r = 0; r < 4; r++) acc[i][j][r] = 0.0f;

    int KT = K / 32;
    const float* W = rg.W;

    // prefetch tile 0
    {
        #pragma unroll
        for (int i = 0; i < 4; i++) {
            int f = tid + i * 256;
            int row = f >> 3, c4 = (f & 7) * 4;
            cp16(bufA[0] + row * 36 + c4, A + (size_t)(m0 + row) * lda + c4);
            cp16(bufB[0] + row * 36 + c4, W + (size_t)(n0 + row) * K + c4);
        }
        asm volatile("cp.async.commit_group;\n");
    }

    for (int kt = 0; kt < KT; kt++) {
        if (kt + 1 < KT) {
            int k0 = (kt + 1) * 32;
            int b = (kt + 1) & 1;
            #pragma unroll
            for (int i = 0; i < 4; i++) {
                int f = tid + i * 256;
                int row = f >> 3, c4 = (f & 7) * 4;
                cp16(bufA[b] + row * 36 + c4, A + (size_t)(m0 + row) * lda + k0 + c4);
                cp16(bufB[b] + row * 36 + c4, W + (size_t)(n0 + row) * K + k0 + c4);
            }
            asm volatile("cp.async.commit_group;\n");
            asm volatile("cp.async.wait_group 1;\n");
        } else {
            asm volatile("cp.async.wait_group 0;\n");
        }
        __syncthreads();

        const float* As = bufA[kt & 1];
        const float* Bs = bufB[kt & 1];
        #pragma unroll
        for (int k8 = 0; k8 < 32; k8 += 8) {
            uint32_t af[4][4], bf[4][2];
            #pragma unroll
            for (int mt = 0; mt < 4; mt++) {
                int mb = wm + mt * 16;
                af[mt][0] = f2tf(As[(mb + lr)     * 36 + k8 + lc]);
                af[mt][1] = f2tf(As[(mb + lr + 8) * 36 + k8 + lc]);
                af[mt][2] = f2tf(As[(mb + lr)     * 36 + k8 + lc + 4]);
                af[mt][3] = f2tf(As[(mb + lr + 8) * 36 + k8 + lc + 4]);
            }
            #pragma unroll
            for (int nt = 0; nt < 4; nt++) {
                int nb = wn + nt * 8;
                bf[nt][0] = f2tf(Bs[(nb + lr) * 36 + k8 + lc]);
                bf[nt][1] = f2tf(Bs[(nb + lr) * 36 + k8 + lc + 4]);
            }
            #pragma unroll
            for (int mt = 0; mt < 4; mt++)
                #pragma unroll
                for (int nt = 0; nt < 4; nt++)
                    mma_tf32(acc[mt][nt], af[mt], bf[nt]);
        }
        __syncthreads();
    }

    // epilogue (float2 stores)
    const float* bias = rg.bias;
    const float* res  = rg.res;
    float* C = rg.C;
    #pragma unroll
    for (int mt = 0; mt < 4; mt++) {
        #pragma unroll
        for (int nt = 0; nt < 4; nt++) {
            int n = n0 + wn + nt * 8 + lc * 2;
            float b0 = 0.0f, b1 = 0.0f;
            if (bias) { b0 = bias[n]; b1 = bias[n + 1]; }
            #pragma unroll
            for (int half = 0; half < 2; half++) {
                int m = mloc0 + wm + mt * 16 + lr + half * 8;
                float v0 = acc[mt][nt][half * 2 + 0] + b0;
                float v1 = acc[mt][nt][half * 2 + 1] + b1;
                if (res) {
                    float2 rr = *(const float2*)(res + (size_t)m * ldres + n);
                    v0 += rr.x; v1 += rr.y;
                }
                *(float2*)(C + (size_t)m * ldc + n) = make_float2(v0, v1);
            }
        }
    }
}

// ---------------- per-head RMSNorm + RoPE on q,k ----------------
__global__ void rmsrope(const float* __restrict__ qk, const float* __restrict__ freqs,
                        const float* __restrict__ px_qn, const float* __restrict__ px_kn,
                        const float* __restrict__ pc_qn, const float* __restrict__ pc_kn,
                        float* __restrict__ q, float* __restrict__ k) {
    int t = blockIdx.x;
    int h = blockIdx.y * 4 + threadIdx.y;
    int lane = threadIdx.x;

    const float* qn = (t < S_C) ? pc_qn : px_qn;
    const float* kn = (t < S_C) ? pc_kn : px_kn;

    const float* src = qk + (size_t)t * (2 * DIM) + h * HD;
    float2 qv = *(const float2*)(src + lane * 2);
    float2 kv = *(const float2*)(src + DIM + lane * 2);

    float qs = qv.x * qv.x + qv.y * qv.y;
    float ks = kv.x * kv.x + kv.y * kv.y;
    #pragma unroll
    for (int o = 16; o > 0; o >>= 1) {
        qs += __shfl_xor_sync(0xFFFFFFFFu, qs, o);
        ks += __shfl_xor_sync(0xFFFFFFFFu, ks, o);
    }
    float qinv = rsqrtf(qs * (1.0f / HD) + 1e-6f);
    float kinv = rsqrtf(ks * (1.0f / HD) + 1e-6f);

    float cosv = freqs[((size_t)t * 32 + lane) * 2 + 0];
    float sinv = freqs[((size_t)t * 32 + lane) * 2 + 1];

    float q0 = qv.x * qinv * qn[lane * 2 + 0];
    float q1 = qv.y * qinv * qn[lane * 2 + 1];
    float k0 = kv.x * kinv * kn[lane * 2 + 0];
    float k1 = kv.y * kinv * kn[lane * 2 + 1];

    size_t base = (size_t)t * DIM + h * HD + lane * 2;
    q[base + 0] = q0 * cosv - q1 * sinv;
    q[base + 1] = q0 * sinv + q1 * cosv;
    k[base + 0] = k0 * cosv - k1 * sinv;
    k[base + 1] = k0 * sinv + k1 * cosv;
}

// ---------------- tiled causal attention (flash-style) ----------------
// QPAD multiple of 4 keeps float4 rows 16B-aligned (272B row stride).
#define QPAD 68
__global__ void __launch_bounds__(256) attn_tiled(
        const float* __restrict__ q, const float* __restrict__ k,
        const float* __restrict__ v, float* __restrict__ y) {
    extern __shared__ float sm[];
    float* QsT = sm;                    // [d][q] transposed
    float* KsT = sm + 64 * QPAD;        // [d][j]
    float* PsT = sm + 2 * 64 * QPAD;    // [j][q]
    float* Vs  = sm + 3 * 64 * QPAD;    // [j][d] natural

    int h = blockIdx.y;
    int qt = blockIdx.x;
    int q0 = qt * 64;
    int tid = threadIdx.x;
    int tx = tid & 15, ty = tid >> 4;

    #pragma unroll
    for (int i = 0; i < 4; i++) {
        int f = tid + i * 256;
        int r = f >> 4, d4 = (f & 15) * 4;
        float4 val = *(const float4*)(q + (size_t)(q0 + r) * DIM + h * HD + d4);
        QsT[(d4 + 0) * QPAD + r] = val.x;
        QsT[(d4 + 1) * QPAD + r] = val.y;
        QsT[(d4 + 2) * QPAD + r] = val.z;
        QsT[(d4 + 3) * QPAD + r] = val.w;
    }

    float m_[4], l_[4], o[4][4];
    #pragma unroll
    for (int i = 0; i < 4; i++) {
        m_[i] = -1e30f; l_[i] = 0.0f;
        #pragma unroll
        for (int j = 0; j < 4; j++) o[i][j] = 0.0f;
    }

    for (int kt = 0; kt <= qt; kt++) {
        int j0 = kt * 64;
        __syncthreads();
        #pragma unroll
        for (int i = 0; i < 4; i++) {
            int f = tid + i * 256;
            int r = f >> 4, d4 = (f & 15) * 4;
            float4 kk = *(const float4*)(k + (size_t)(j0 + r) * DIM + h * HD + d4);
            KsT[(d4 + 0) * QPAD + r] = kk.x;
            KsT[(d4 + 1) * QPAD + r] = kk.y;
            KsT[(d4 + 2) * QPAD + r] = kk.z;
            KsT[(d4 + 3) * QPAD + r] = kk.w;
            float4 vv = *(const float4*)(v + (size_t)(j0 + r) * DIM + h * HD + d4);
            *(float4*)(Vs + r * 64 + d4) = vv;
        }
        __syncthreads();

        float s[4][4] = {};
        #pragma unroll 8
        for (int d = 0; d < 64; d++) {
            float4 a = *(const float4*)(QsT + d * QPAD + ty * 4);
            float4 b = *(const float4*)(KsT + d * QPAD + tx * 4);
            float aa[4] = {a.x, a.y, a.z, a.w};
            float bb[4] = {b.x, b.y, b.z, b.w};
            #pragma unroll
            for (int i = 0; i < 4; i++)
                #pragma unroll
                for (int jj = 0; jj < 4; jj++)
                    s[i][jj] = fmaf(aa[i], bb[jj], s[i][jj]);
        }

        bool diag = (kt == qt);
        #pragma unroll
        for (int i = 0; i < 4; i++)
            #pragma unroll
            for (int jj = 0; jj < 4; jj++) {
                float sv = s[i][jj] * 0.125f;
                if (diag && (tx * 4 + jj) > (ty * 4 + i)) sv = -1e30f;
                s[i][jj] = sv;
            }

        #pragma unroll
        for (int i = 0; i < 4; i++) {
            float mx = fmaxf(fmaxf(s[i][0], s[i][1]), fmaxf(s[i][2], s[i][3]));
            #pragma unroll
            for (int off = 8; off > 0; off >>= 1)
                mx = fmaxf(mx, __shfl_xor_sync(0xFFFFFFFFu, mx, off));
            float nm = fmaxf(m_[i], mx);
            float f_ = __expf(m_[i] - nm);
            float rs = 0.0f;
            #pragma unroll
            for (int jj = 0; jj < 4; jj++) {
                float p = __expf(s[i][jj] - nm);
                s[i][jj] = p;
                rs += p;
            }
            #pragma unroll
            for (int off = 8; off > 0; off >>= 1)
                rs += __shfl_xor_sync(0xFFFFFFFFu, rs, off);
            l_[i] = l_[i] * f_ + rs;
            m_[i] = nm;
            #pragma unroll
            for (int jj = 0; jj < 4; jj++) o[i][jj] *= f_;
            #pragma unroll
            for (int jj = 0; jj < 4; jj++)
                PsT[(tx * 4 + jj) * QPAD + ty * 4 + i] = s[i][jj];
        }
        __syncthreads();

        #pragma unroll 8
        for (int j = 0; j < 64; j++) {
            float4 a = *(const float4*)(PsT + j * QPAD + ty * 4);
            float4 b = *(const float4*)(Vs + j * 64 + tx * 4);
            float aa[4] = {a.x, a.y, a.z, a.w};
            float bb[4] = {b.x, b.y, b.z, b.w};
            #pragma unroll
            for (int i = 0; i < 4; i++)
                #pragma unroll
                for (int jj = 0; jj < 4; jj++)
                    o[i][jj] = fmaf(aa[i], bb[jj], o[i][jj]);
        }
    }

    #pragma unroll
    for (int i = 0; i < 4; i++) {
        float inv = 1.0f / l_[i];
        #pragma unroll
        for (int jj = 0; jj < 4; jj++)
            y[(size_t)(q0 + ty * 4 + i) * DIM + h * HD + tx * 4 + jj] = o[i][jj] * inv;
    }
}

// ---------------- SwiGLU gate: a = silu(a) * b ----------------
__global__ void silu_mul(float* __restrict__ a, const float* __restrict__ b, int n4) {
    int i = blockIdx.x * blockDim.x + threadIdx.x;
    if (i < n4) {
        float4 av = ((float4*)a)[i];
        float4 bv = ((const float4*)b)[i];
        av.x = av.x / (1.0f + __expf(-av.x)) * bv.x;
        av.y = av.y / (1.0f + __expf(-av.y)) * bv.y;
        av.z = av.z / (1.0f + __expf(-av.z)) * bv.z;
        av.w = av.w / (1.0f + __expf(-av.w)) * bv.w;
        ((float4*)a)[i] = av;
    }
}

// ---------------- launch ----------------
#define GEMM_SMEM (4 * 128 * 36 * 4)                 // 73728 B
#define ATTN_SMEM ((3 * 64 * QPAD + 64 * 64) * 4)    // 68608 B

extern "C" void kernel_launch(void* const* d_in, const int* in_sizes, int n_in,
                              void* d_out, int out_size) {
    const float* x        = (const float*)d_in[0];
    const float* c        = (const float*)d_in[1];
    const float* freqs    = (const float*)d_in[2];
    const float* px_qk_w  = (const float*)d_in[3];
    const float* px_qn    = (const float*)d_in[4];
    const float* px_kn    = (const float*)d_in[5];
    const float* px_v_w   = (const float*)d_in[6];
    const float* px_v_b   = (const float*)d_in[7];
    const float* pc_qk_w  = (const float*)d_in[8];
    const float* pc_qn    = (const float*)d_in[9];
    const float* pc_kn    = (const float*)d_in[10];
    const float* pc_v_w   = (const float*)d_in[11];
    const float* pc_v_b   = (const float*)d_in[12];
    const float* p1_proj_w= (const float*)d_in[13];
    const float* p1_proj_b= (const float*)d_in[14];
    const float* p1_w1    = (const float*)d_in[15];
    const float* p1_b1    = (const float*)d_in[16];
    const float* p1_w3    = (const float*)d_in[17];
    const float* p1_b3    = (const float*)d_in[18];
    const float* p1_w2    = (const float*)d_in[19];
    const float* p1_b2    = (const float*)d_in[20];
    const float* p2_proj_w= (const float*)d_in[21];
    const float* p2_proj_b= (const float*)d_in[22];
    const float* p2_w1    = (const float*)d_in[23];
    const float* p2_b1    = (const float*)d_in[24];
    const float* p2_w3    = (const float*)d_in[25];
    const float* p2_b3    = (const float*)d_in[26];
    const float* p2_w2    = (const float*)d_in[27];
    const float* p2_b2    = (const float*)d_in[28];
    float* out = (float*)d_out;

    float *ln_, *qk_, *q_, *k_, *v_, *y_, *x1_, *ln2_, *ff1_, *ff3_;
    cudaGetSymbolAddress((void**)&ln_,  g_ln);
    cudaGetSymbolAddress((void**)&qk_,  g_qk);
    cudaGetSymbolAddress((void**)&q_,   g_q);
    cudaGetSymbolAddress((void**)&k_,   g_k);
    cudaGetSymbolAddress((void**)&v_,   g_v);
    cudaGetSymbolAddress((void**)&y_,   g_y);
    cudaGetSymbolAddress((void**)&x1_,  g_x1);
    cudaGetSymbolAddress((void**)&ln2_, g_ln2);
    cudaGetSymbolAddress((void**)&ff1_, g_ff1);
    cudaGetSymbolAddress((void**)&ff3_, g_ff3);

    cudaFuncSetAttribute(gemm_tf32, cudaFuncAttributeMaxDynamicSharedMemorySize, GEMM_SMEM);
    cudaFuncSetAttribute(attn_tiled, cudaFuncAttributeMaxDynamicSharedMemorySize, ATTN_SMEM);

    // 1. LN on both streams into unified [c; x] token order
    ln_concat<<<T_TOK, 256>>>(x, c, ln_);

    // 2. qk projection — one launch over all 2048 rows, per-region weights
    {
        Region r0 = { pc_qk_w, nullptr, nullptr, qk_ };
        Region r1 = { px_qk_w, nullptr, nullptr, qk_ + (size_t)S_C * 2 * DIM };
        gemm_tf32<<<dim3(2 * DIM / 128, T_TOK / 128), 256, GEMM_SMEM>>>(
            ln_, DIM, r0, r1, 0, 2 * DIM, DIM);
    }

    // 3. v projection (+bias)
    {
        Region r0 = { pc_v_w, pc_v_b, nullptr, v_ };
        Region r1 = { px_v_w, px_v_b, nullptr, v_ + (size_t)S_C * DIM };
        gemm_tf32<<<dim3(DIM / 128, T_TOK / 128), 256, GEMM_SMEM>>>(
            ln_, DIM, r0, r1, 0, DIM, DIM);
    }

    // 4. per-head RMSNorm + RoPE
    rmsrope<<<dim3(T_TOK, NH / 4), dim3(32, 4)>>>(qk_, freqs, px_qn, px_kn, pc_qn, pc_kn, q_, k_);

    // 5. tiled causal attention
    attn_tiled<<<dim3(T_TOK / 64, NH), 256, ATTN_SMEM>>>(q_, k_, v_, y_);

    // 6. output projection + residual
    {
        Region r0 = { p2_proj_w, p2_proj_b, c, x1_ };
        Region r1 = { p1_proj_w, p1_proj_b, x, x1_ + (size_t)S_C * DIM };
        gemm_tf32<<<dim3(DIM / 128, T_TOK / 128), 256, GEMM_SMEM>>>(
            y_, DIM, r0, r1, DIM, DIM, DIM);
    }

    // 7. second LN
    ln_rows<<<T_TOK, 256>>>(x1_, ln2_);

    // 8. MLP up projections (w1 and w3)
    {
        Region r0 = { p2_w1, p2_b1, nullptr, ff1_ };
        Region r1 = { p1_w1, p1_b1, nullptr, ff1_ + (size_t)S_C * FFD };
        gemm_tf32<<<dim3(FFD / 128, T_TOK / 128), 256, GEMM_SMEM>>>(
            ln2_, DIM, r0, r1, 0, FFD, DIM);
    }
    {
        Region r0 = { p2_w3, p2_b3, nullptr, ff3_ };
        Region r1 = { p1_w3, p1_b3, nullptr, ff3_ + (size_t)S_C * FFD };
        gemm_tf32<<<dim3(FFD / 128, T_TOK / 128), 256, GEMM_SMEM>>>(
            ln2_, DIM, r0, r1, 0, FFD, DIM);
    }

    // 9. SwiGLU gate
    {
        int n4 = T_TOK * FFD / 4;
        silu_mul<<<(n4 + 255) / 256, 256>>>(ff1_, ff3_, n4);
    }

    // 10. MLP down projection + residual -> final outputs (x_out first, then c_out)
    {
        Region r0 = { p2_w2, p2_b2, x1_,                     out + (size_t)L_X * DIM };
        Region r1 = { p1_w2, p1_b2, x1_ + (size_t)S_C * DIM, out };
        gemm_tf32<<<dim3(DIM / 128, T_TOK / 128), 256, GEMM_SMEM>>>(
            ff1_, FFD, r0, r1, DIM, DIM, FFD);
    }
}

// round 8
// speedup vs baseline: 4.5865x; 1.0651x over previous
#include <cuda_runtime.h>
#include <cstdint>
#include <math.h>

#define T_TOK 2048
#define S_C   512
#define L_X   1536
#define DIM   1024
#define NH    16
#define HD    64
#define FFD   4096

// ---------------- static scratch (no allocations allowed) ----------------
__device__ float g_ln  [T_TOK * DIM];
__device__ float g_qkv [T_TOK * 3 * DIM];     // cols: q[0,1024) k[1024,2048) v[2048,3072)
__device__ float g_q   [T_TOK * DIM];
__device__ float g_k   [T_TOK * DIM];
__device__ float g_y   [T_TOK * DIM];
__device__ float g_x1  [T_TOK * DIM];
__device__ float g_ln2 [T_TOK * DIM];
__device__ float g_ff1 [T_TOK * FFD];
__device__ float g_ff3 [T_TOK * FFD];
__device__ float g_part[2 * T_TOK * DIM];     // split-K partials

// ---------------- small helpers ----------------
__device__ __forceinline__ uint32_t f2tf(float x) {
    uint32_t r;
    asm("cvt.rna.tf32.f32 %0, %1;" : "=r"(r) : "f"(x));
    return r;
}

__device__ __forceinline__ void mma_tf32(float* c, const uint32_t* a, const uint32_t* b) {
    asm volatile(
        "mma.sync.aligned.m16n8k8.row.col.f32.tf32.tf32.f32 "
        "{%0,%1,%2,%3}, {%4,%5,%6,%7}, {%8,%9}, {%0,%1,%2,%3};\n"
        : "+f"(c[0]), "+f"(c[1]), "+f"(c[2]), "+f"(c[3])
        : "r"(a[0]), "r"(a[1]), "r"(a[2]), "r"(a[3]), "r"(b[0]), "r"(b[1]));
}

__device__ __forceinline__ void cp16(void* s, const void* g) {
    uint32_t sa = (uint32_t)__cvta_generic_to_shared(s);
    asm volatile("cp.async.cg.shared.global [%0], [%1], 16;\n" :: "r"(sa), "l"(g));
}

// GEMM region table: m-region (c vs x stream) x n-region (two weight sets).
struct GR {
    const float* W[2][2];
    const float* bias[2][2];
    const float* res[2];
    float* C[2][2];
};

// ---------------- LayerNorm over concat([c, x]) rows ----------------
__global__ void ln_concat(const float* __restrict__ x, const float* __restrict__ c,
                          float* __restrict__ out) {
    int row = blockIdx.x;
    const float* src = (row < S_C) ? (c + (size_t)row * DIM)
                                   : (x + (size_t)(row - S_C) * DIM);
    float* dst = out + (size_t)row * DIM;
    __shared__ float red[256];
    int tid = threadIdx.x;

    float4 v = ((const float4*)src)[tid];
    red[tid] = v.x + v.y + v.z + v.w; __syncthreads();
    for (int o = 128; o > 0; o >>= 1) { if (tid < o) red[tid] += red[tid + o]; __syncthreads(); }
    float mean = red[0] * (1.0f / DIM);
    __syncthreads();

    float dx = v.x - mean, dy = v.y - mean, dz = v.z - mean, dw = v.w - mean;
    red[tid] = dx*dx + dy*dy + dz*dz + dw*dw; __syncthreads();
    for (int o = 128; o > 0; o >>= 1) { if (tid < o) red[tid] += red[tid + o]; __syncthreads(); }
    float inv = rsqrtf(red[0] * (1.0f / DIM) + 1e-6f);

    ((float4*)dst)[tid] = make_float4(dx * inv, dy * inv, dz * inv, dw * inv);
}

__global__ void ln_rows(const float* __restrict__ in, float* __restrict__ out) {
    int row = blockIdx.x;
    const float* src = in + (size_t)row * DIM;
    float* dst = out + (size_t)row * DIM;
    __shared__ float red[256];
    int tid = threadIdx.x;

    float4 v = ((const float4*)src)[tid];
    red[tid] = v.x + v.y + v.z + v.w; __syncthreads();
    for (int o = 128; o > 0; o >>= 1) { if (tid < o) red[tid] += red[tid + o]; __syncthreads(); }
    float mean = red[0] * (1.0f / DIM);
    __syncthreads();

    float dx = v.x - mean, dy = v.y - mean, dz = v.z - mean, dw = v.w - mean;
    red[tid] = dx*dx + dy*dy + dz*dz + dw*dw; __syncthreads();
    for (int o = 128; o > 0; o >>= 1) { if (tid < o) red[tid] += red[tid + o]; __syncthreads(); }
    float inv = rsqrtf(red[0] * (1.0f / DIM) + 1e-6f);

    ((float4*)dst)[tid] = make_float4(dx * inv, dy * inv, dz * inv, dw * inv);
}

// ---------------- tf32 tensor-core GEMM, region-fused, optional split-K -------
// A: [2048, K] contiguous global rows. m-tile < SPLIT_MT -> m-region 0 (c) else 1 (x).
// n-tile < nsplit -> n-region 0 else 1 (region-local cols). If part != null: write
// raw partials at global rows into part[z][2048][DIM] (ldc must be DIM), no bias/res.
#define SPLIT_MT (S_C / 128)
__global__ void __launch_bounds__(256, 2) gemm_tf32(
        const float* __restrict__ A, int lda,
        GR g, int nsplit, int ldres, int ldc, int K, int ksplit,
        float* __restrict__ part) {
    extern __shared__ float sm[];
    const int ASZ = 128 * 36;
    float* bufA[2] = { sm,       sm + 2 * ASZ };
    float* bufB[2] = { sm + ASZ, sm + 3 * ASZ };

    int tid = threadIdx.x;
    int mt0 = blockIdx.y, nt0 = blockIdx.x;
    int mr = (mt0 < SPLIT_MT) ? 0 : 1;
    int nr = (nt0 < nsplit) ? 0 : 1;
    int m0 = mt0 * 128;
    int mloc0 = m0 - (mr ? S_C : 0);
    int nloc0 = (nt0 - (nr ? nsplit : 0)) * 128;
    const float* W = g.W[mr][nr];

    int KT = K / 32;
    int KTz = KT / ksplit;
    int kbase = blockIdx.z * KTz * 32;
    const float* AP = A + kbase;
    const float* WP = W + kbase;

    int wid = tid >> 5, lane = tid & 31;
    int wm = (wid >> 2) * 64;
    int wn = (wid & 3) * 32;
    int lr = lane >> 2;
    int lc = lane & 3;

    float acc[4][4][4];
    #pragma unroll
    for (int i = 0; i < 4; i++)
        #pragma unroll
        for (int j = 0; j < 4; j++)
            #pragma unroll
            for (int r = 0; r < 4; r++) acc[i][j][r] = 0.0f;

    // prefetch tile 0
    {
        #pragma unroll
        for (int i = 0; i < 4; i++) {
            int f = tid + i * 256;
            int row = f >> 3, c4 = (f & 7) * 4;
            cp16(bufA[0] + row * 36 + c4, AP + (size_t)(m0 + row) * lda + c4);
            cp16(bufB[0] + row * 36 + c4, WP + (size_t)(nloc0 + row) * K + c4);
        }
        asm volatile("cp.async.commit_group;\n");
    }

    for (int kt = 0; kt < KTz; kt++) {
        if (kt + 1 < KTz) {
            int k0 = (kt + 1) * 32;
            int b = (kt + 1) & 1;
            #pragma unroll
            for (int i = 0; i < 4; i++) {
                int f = tid + i * 256;
                int row = f >> 3, c4 = (f & 7) * 4;
                cp16(bufA[b] + row * 36 + c4, AP + (size_t)(m0 + row) * lda + k0 + c4);
                cp16(bufB[b] + row * 36 + c4, WP + (size_t)(nloc0 + row) * K + k0 + c4);
            }
            asm volatile("cp.async.commit_group;\n");
            asm volatile("cp.async.wait_group 1;\n");
        } else {
            asm volatile("cp.async.wait_group 0;\n");
        }
        __syncthreads();

        const float* As = bufA[kt & 1];
        const float* Bs = bufB[kt & 1];
        #pragma unroll
        for (int k8 = 0; k8 < 32; k8 += 8) {
            uint32_t af[4][4], bf[4][2];
            #pragma unroll
            for (int mt = 0; mt < 4; mt++) {
                int mb = wm + mt * 16;
                af[mt][0] = f2tf(As[(mb + lr)     * 36 + k8 + lc]);
                af[mt][1] = f2tf(As[(mb + lr + 8) * 36 + k8 + lc]);
                af[mt][2] = f2tf(As[(mb + lr)     * 36 + k8 + lc + 4]);
                af[mt][3] = f2tf(As[(mb + lr + 8) * 36 + k8 + lc + 4]);
            }
            #pragma unroll
            for (int nt = 0; nt < 4; nt++) {
                int nb = wn + nt * 8;
                bf[nt][0] = f2tf(Bs[(nb + lr) * 36 + k8 + lc]);
                bf[nt][1] = f2tf(Bs[(nb + lr) * 36 + k8 + lc + 4]);
            }
            #pragma unroll
            for (int mt = 0; mt < 4; mt++)
                #pragma unroll
                for (int nt = 0; nt < 4; nt++)
                    mma_tf32(acc[mt][nt], af[mt], bf[nt]);
        }
        __syncthreads();
    }

    if (part) {
        // raw partial at global rows, ldc = DIM
        float* P = part + ((size_t)blockIdx.z * T_TOK + m0) * DIM;
        #pragma unroll
        for (int mt = 0; mt < 4; mt++)
            #pragma unroll
            for (int nt = 0; nt < 4; nt++) {
                int n = nloc0 + wn + nt * 8 + lc * 2;
                #pragma unroll
                for (int half = 0; half < 2; half++) {
                    int m = wm + mt * 16 + lr + half * 8;
                    *(float2*)(P + (size_t)m * DIM + n) =
                        make_float2(acc[mt][nt][half * 2 + 0], acc[mt][nt][half * 2 + 1]);
                }
            }
        return;
    }

    const float* bias = g.bias[mr][nr];
    const float* res  = g.res[mr];
    float* C = g.C[mr][nr];
    #pragma unroll
    for (int mt = 0; mt < 4; mt++) {
        #pragma unroll
        for (int nt = 0; nt < 4; nt++) {
            int n = nloc0 + wn + nt * 8 + lc * 2;
            float b0 = 0.0f, b1 = 0.0f;
            if (bias) { b0 = bias[n]; b1 = bias[n + 1]; }
            #pragma unroll
            for (int half = 0; half < 2; half++) {
                int m = mloc0 + wm + mt * 16 + lr + half * 8;
                float v0 = acc[mt][nt][half * 2 + 0] + b0;
                float v1 = acc[mt][nt][half * 2 + 1] + b1;
                if (res) {
                    float2 rr = *(const float2*)(res + (size_t)m * ldres + n);
                    v0 += rr.x; v1 += rr.y;
                }
                *(float2*)(C + (size_t)m * ldc + n) = make_float2(v0, v1);
            }
        }
    }
}

// ---------------- split-K=2 reduce: C = p0 + p1 + bias + res (per m-region) ----
__global__ void reduce_split2(const float* __restrict__ part,
        const float* __restrict__ b0, const float* __restrict__ b1,
        const float* __restrict__ r0, const float* __restrict__ r1,
        float* __restrict__ C0, float* __restrict__ C1) {
    int row = blockIdx.x;
    int col = threadIdx.x * 4;
    float4 p = *(const float4*)(part + (size_t)row * DIM + col);
    float4 q = *(const float4*)(part + (size_t)(T_TOK + row) * DIM + col);
    const float* bias; const float* res; float* C; int lr_;
    if (row < S_C) { bias = b0; res = r0; C = C0; lr_ = row; }
    else           { bias = b1; res = r1; C = C1; lr_ = row - S_C; }
    float4 bb = *(const float4*)(bias + col);
    float4 rr = *(const float4*)(res + (size_t)lr_ * DIM + col);
    float4 o;
    o.x = p.x + q.x + bb.x + rr.x;
    o.y = p.y + q.y + bb.y + rr.y;
    o.z = p.z + q.z + bb.z + rr.z;
    o.w = p.w + q.w + bb.w + rr.w;
    *(float4*)(C + (size_t)lr_ * DIM + col) = o;
}

// ---------------- per-head RMSNorm + RoPE on q,k (from packed qkv) ------------
__global__ void rmsrope(const float* __restrict__ qkv, const float* __restrict__ freqs,
                        const float* __restrict__ px_qn, const float* __restrict__ px_kn,
                        const float* __restrict__ pc_qn, const float* __restrict__ pc_kn,
                        float* __restrict__ q, float* __restrict__ k) {
    int t = blockIdx.x;
    int h = blockIdx.y * 4 + threadIdx.y;
    int lane = threadIdx.x;

    const float* qn = (t < S_C) ? pc_qn : px_qn;
    const float* kn = (t < S_C) ? pc_kn : px_kn;

    const float* src = qkv + (size_t)t * (3 * DIM) + h * HD;
    float2 qv = *(const float2*)(src + lane * 2);
    float2 kv = *(const float2*)(src + DIM + lane * 2);

    float qs = qv.x * qv.x + qv.y * qv.y;
    float ks = kv.x * kv.x + kv.y * kv.y;
    #pragma unroll
    for (int o = 16; o > 0; o >>= 1) {
        qs += __shfl_xor_sync(0xFFFFFFFFu, qs, o);
        ks += __shfl_xor_sync(0xFFFFFFFFu, ks, o);
    }
    float qinv = rsqrtf(qs * (1.0f / HD) + 1e-6f);
    float kinv = rsqrtf(ks * (1.0f / HD) + 1e-6f);

    float cosv = freqs[((size_t)t * 32 + lane) * 2 + 0];
    float sinv = freqs[((size_t)t * 32 + lane) * 2 + 1];

    float q0 = qv.x * qinv * qn[lane * 2 + 0];
    float q1 = qv.y * qinv * qn[lane * 2 + 1];
    float k0 = kv.x * kinv * kn[lane * 2 + 0];
    float k1 = kv.y * kinv * kn[lane * 2 + 1];

    size_t base = (size_t)t * DIM + h * HD + lane * 2;
    q[base + 0] = q0 * cosv - q1 * sinv;
    q[base + 1] = q0 * sinv + q1 * cosv;
    k[base + 0] = k0 * cosv - k1 * sinv;
    k[base + 1] = k0 * sinv + k1 * cosv;
}

// ---------------- tiled causal attention (flash-style) ----------------
#define QPAD 68
__global__ void __launch_bounds__(256) attn_tiled(
        const float* __restrict__ q, const float* __restrict__ k,
        const float* __restrict__ v, int vld, float* __restrict__ y) {
    extern __shared__ float sm[];
    float* QsT = sm;                    // [d][q] transposed
    float* KsT = sm + 64 * QPAD;        // [d][j]
    float* PsT = sm + 2 * 64 * QPAD;    // [j][q]
    float* Vs  = sm + 3 * 64 * QPAD;    // [j][d]

    int h = blockIdx.y;
    int qt = blockIdx.x;
    int q0 = qt * 64;
    int tid = threadIdx.x;
    int tx = tid & 15, ty = tid >> 4;

    #pragma unroll
    for (int i = 0; i < 4; i++) {
        int f = tid + i * 256;
        int r = f >> 4, d4 = (f & 15) * 4;
        float4 val = *(const float4*)(q + (size_t)(q0 + r) * DIM + h * HD + d4);
        QsT[(d4 + 0) * QPAD + r] = val.x;
        QsT[(d4 + 1) * QPAD + r] = val.y;
        QsT[(d4 + 2) * QPAD + r] = val.z;
        QsT[(d4 + 3) * QPAD + r] = val.w;
    }

    float m_[4], l_[4], o[4][4];
    #pragma unroll
    for (int i = 0; i < 4; i++) {
        m_[i] = -1e30f; l_[i] = 0.0f;
        #pragma unroll
        for (int j = 0; j < 4; j++) o[i][j] = 0.0f;
    }

    for (int kt = 0; kt <= qt; kt++) {
        int j0 = kt * 64;
        __syncthreads();
        #pragma unroll
        for (int i = 0; i < 4; i++) {
            int f = tid + i * 256;
            int r = f >> 4, d4 = (f & 15) * 4;
            float4 kk = *(const float4*)(k + (size_t)(j0 + r) * DIM + h * HD + d4);
            KsT[(d4 + 0) * QPAD + r] = kk.x;
            KsT[(d4 + 1) * QPAD + r] = kk.y;
            KsT[(d4 + 2) * QPAD + r] = kk.z;
            KsT[(d4 + 3) * QPAD + r] = kk.w;
            float4 vv = *(const float4*)(v + (size_t)(j0 + r) * vld + h * HD + d4);
            *(float4*)(Vs + r * 64 + d4) = vv;
        }
        __syncthreads();

        float s[4][4] = {};
        #pragma unroll 8
        for (int d = 0; d < 64; d++) {
            float4 a = *(const float4*)(QsT + d * QPAD + ty * 4);
            float4 b = *(const float4*)(KsT + d * QPAD + tx * 4);
            float aa[4] = {a.x, a.y, a.z, a.w};
            float bb[4] = {b.x, b.y, b.z, b.w};
            #pragma unroll
            for (int i = 0; i < 4; i++)
                #pragma unroll
                for (int jj = 0; jj < 4; jj++)
                    s[i][jj] = fmaf(aa[i], bb[jj], s[i][jj]);
        }

        bool diag = (kt == qt);
        #pragma unroll
        for (int i = 0; i < 4; i++)
            #pragma unroll
            for (int jj = 0; jj < 4; jj++) {
                float sv = s[i][jj] * 0.125f;
                if (diag && (tx * 4 + jj) > (ty * 4 + i)) sv = -1e30f;
                s[i][jj] = sv;
            }

        #pragma unroll
        for (int i = 0; i < 4; i++) {
            float mx = fmaxf(fmaxf(s[i][0], s[i][1]), fmaxf(s[i][2], s[i][3]));
            #pragma unroll
            for (int off = 8; off > 0; off >>= 1)
                mx = fmaxf(mx, __shfl_xor_sync(0xFFFFFFFFu, mx, off));
            float nm = fmaxf(m_[i], mx);
            float f_ = __expf(m_[i] - nm);
            float rs = 0.0f;
            #pragma unroll
            for (int jj = 0; jj < 4; jj++) {
                float p = __expf(s[i][jj] - nm);
                s[i][jj] = p;
                rs += p;
            }
            #pragma unroll
            for (int off = 8; off > 0; off >>= 1)
                rs += __shfl_xor_sync(0xFFFFFFFFu, rs, off);
            l_[i] = l_[i] * f_ + rs;
            m_[i] = nm;
            #pragma unroll
            for (int jj = 0; jj < 4; jj++) o[i][jj] *= f_;
            #pragma unroll
            for (int jj = 0; jj < 4; jj++)
                PsT[(tx * 4 + jj) * QPAD + ty * 4 + i] = s[i][jj];
        }
        __syncthreads();

        #pragma unroll 8
        for (int j = 0; j < 64; j++) {
            float4 a = *(const float4*)(PsT + j * QPAD + ty * 4);
            float4 b = *(const float4*)(Vs + j * 64 + tx * 4);
            float aa[4] = {a.x, a.y, a.z, a.w};
            float bb[4] = {b.x, b.y, b.z, b.w};
            #pragma unroll
            for (int i = 0; i < 4; i++)
                #pragma unroll
                for (int jj = 0; jj < 4; jj++)
                    o[i][jj] = fmaf(aa[i], bb[jj], o[i][jj]);
        }
    }

    #pragma unroll
    for (int i = 0; i < 4; i++) {
        float inv = 1.0f / l_[i];
        #pragma unroll
        for (int jj = 0; jj < 4; jj++)
            y[(size_t)(q0 + ty * 4 + i) * DIM + h * HD + tx * 4 + jj] = o[i][jj] * inv;
    }
}

// ---------------- SwiGLU gate: a = silu(a) * b ----------------
__global__ void silu_mul(float* __restrict__ a, const float* __restrict__ b, int n4) {
    int i = blockIdx.x * blockDim.x + threadIdx.x;
    if (i < n4) {
        float4 av = ((float4*)a)[i];
        float4 bv = ((const float4*)b)[i];
        av.x = av.x / (1.0f + __expf(-av.x)) * bv.x;
        av.y = av.y / (1.0f + __expf(-av.y)) * bv.y;
        av.z = av.z / (1.0f + __expf(-av.z)) * bv.z;
        av.w = av.w / (1.0f + __expf(-av.w)) * bv.w;
        ((float4*)a)[i] = av;
    }
}

// ---------------- launch ----------------
#define GEMM_SMEM (4 * 128 * 36 * 4)                 // 73728 B
#define ATTN_SMEM ((3 * 64 * QPAD + 64 * 64) * 4)    // 68608 B

extern "C" void kernel_launch(void* const* d_in, const int* in_sizes, int n_in,
                              void* d_out, int out_size) {
    const float* x        = (const float*)d_in[0];
    const float* c        = (const float*)d_in[1];
    const float* freqs    = (const float*)d_in[2];
    const float* px_qk_w  = (const float*)d_in[3];
    const float* px_qn    = (const float*)d_in[4];
    const float* px_kn    = (const float*)d_in[5];
    const float* px_v_w   = (const float*)d_in[6];
    const float* px_v_b   = (const float*)d_in[7];
    const float* pc_qk_w  = (const float*)d_in[8];
    const float* pc_qn    = (const float*)d_in[9];
    const float* pc_kn    = (const float*)d_in[10];
    const float* pc_v_w   = (const float*)d_in[11];
    const float* pc_v_b   = (const float*)d_in[12];
    const float* p1_proj_w= (const float*)d_in[13];
    const float* p1_proj_b= (const float*)d_in[14];
    const float* p1_w1    = (const float*)d_in[15];
    const float* p1_b1    = (const float*)d_in[16];
    const float* p1_w3    = (const float*)d_in[17];
    const float* p1_b3    = (const float*)d_in[18];
    const float* p1_w2    = (const float*)d_in[19];
    const float* p1_b2    = (const float*)d_in[20];
    const float* p2_proj_w= (const float*)d_in[21];
    const float* p2_proj_b= (const float*)d_in[22];
    const float* p2_w1    = (const float*)d_in[23];
    const float* p2_b1    = (const float*)d_in[24];
    const float* p2_w3    = (const float*)d_in[25];
    const float* p2_b3    = (const float*)d_in[26];
    const float* p2_w2    = (const float*)d_in[27];
    const float* p2_b2    = (const float*)d_in[28];
    float* out = (float*)d_out;

    float *ln_, *qkv_, *q_, *k_, *y_, *x1_, *ln2_, *ff1_, *ff3_, *part_;
    cudaGetSymbolAddress((void**)&ln_,  g_ln);
    cudaGetSymbolAddress((void**)&qkv_, g_qkv);
    cudaGetSymbolAddress((void**)&q_,   g_q);
    cudaGetSymbolAddress((void**)&k_,   g_k);
    cudaGetSymbolAddress((void**)&y_,   g_y);
    cudaGetSymbolAddress((void**)&x1_,  g_x1);
    cudaGetSymbolAddress((void**)&ln2_, g_ln2);
    cudaGetSymbolAddress((void**)&ff1_, g_ff1);
    cudaGetSymbolAddress((void**)&ff3_, g_ff3);
    cudaGetSymbolAddress((void**)&part_, g_part);

    cudaFuncSetAttribute(gemm_tf32, cudaFuncAttributeMaxDynamicSharedMemorySize, GEMM_SMEM);
    cudaFuncSetAttribute(attn_tiled, cudaFuncAttributeMaxDynamicSharedMemorySize, ATTN_SMEM);

    // 1. LN on both streams into unified [c; x] token order
    ln_concat<<<T_TOK, 256>>>(x, c, ln_);

    // 2+3. fused qkv projection: n-tiles 0-15 -> qk weights, 16-23 -> v weights
    {
        GR g = {};
        g.W[0][0] = pc_qk_w;  g.W[0][1] = pc_v_w;
        g.W[1][0] = px_qk_w;  g.W[1][1] = px_v_w;
        g.bias[0][1] = pc_v_b; g.bias[1][1] = px_v_b;
        g.C[0][0] = qkv_;                           g.C[0][1] = qkv_ + 2 * DIM;
        g.C[1][0] = qkv_ + (size_t)S_C * 3 * DIM;   g.C[1][1] = qkv_ + (size_t)S_C * 3 * DIM + 2 * DIM;
        gemm_tf32<<<dim3(24, T_TOK / 128, 1), 256, GEMM_SMEM>>>(
            ln_, DIM, g, 16, 0, 3 * DIM, DIM, 1, nullptr);
    }

    // 4. per-head RMSNorm + RoPE
    rmsrope<<<dim3(T_TOK, NH / 4), dim3(32, 4)>>>(qkv_, freqs, px_qn, px_kn, pc_qn, pc_kn, q_, k_);

    // 5. tiled causal attention (v packed in qkv, stride 3072)
    attn_tiled<<<dim3(T_TOK / 64, NH), 256, ATTN_SMEM>>>(q_, k_, qkv_ + 2 * DIM, 3 * DIM, y_);

    // 6. output projection, split-K=2 -> partials, then reduce (+bias +res)
    {
        GR g = {};
        g.W[0][0] = p2_proj_w;  g.W[1][0] = p1_proj_w;
        gemm_tf32<<<dim3(DIM / 128, T_TOK / 128, 2), 256, GEMM_SMEM>>>(
            y_, DIM, g, 1000, 0, DIM, DIM, 2, part_);
        reduce_split2<<<T_TOK, 256>>>(part_, p2_proj_b, p1_proj_b, c, x,
                                      x1_, x1_ + (size_t)S_C * DIM);
    }

    // 7. second LN
    ln_rows<<<T_TOK, 256>>>(x1_, ln2_);

    // 8. fused MLP up projection: n-tiles 0-31 -> w1, 32-63 -> w3
    {
        GR g = {};
        g.W[0][0] = p2_w1;  g.W[0][1] = p2_w3;
        g.W[1][0] = p1_w1;  g.W[1][1] = p1_w3;
        g.bias[0][0] = p2_b1; g.bias[0][1] = p2_b3;
        g.bias[1][0] = p1_b1; g.bias[1][1] = p1_b3;
        g.C[0][0] = ff1_;                        g.C[0][1] = ff3_;
        g.C[1][0] = ff1_ + (size_t)S_C * FFD;    g.C[1][1] = ff3_ + (size_t)S_C * FFD;
        gemm_tf32<<<dim3(64, T_TOK / 128, 1), 256, GEMM_SMEM>>>(
            ln2_, DIM, g, 32, 0, FFD, DIM, 1, nullptr);
    }

    // 9. SwiGLU gate
    {
        int n4 = T_TOK * FFD / 4;
        silu_mul<<<(n4 + 255) / 256, 256>>>(ff1_, ff3_, n4);
    }

    // 10. MLP down projection, split-K=2 -> partials, then reduce (+bias +res)
    {
        GR g = {};
        g.W[0][0] = p2_w2;  g.W[1][0] = p1_w2;
        gemm_tf32<<<dim3(DIM / 128, T_TOK / 128, 2), 256, GEMM_SMEM>>>(
            ff1_, FFD, g, 1000, 0, DIM, FFD, 2, part_);
        reduce_split2<<<T_TOK, 256>>>(part_, p2_b2, p1_b2, x1_, x1_ + (size_t)S_C * DIM,
                                      out + (size_t)L_X * DIM, out);
    }
}

// round 10
// speedup vs baseline: 6.1196x; 1.3343x over previous
#include <cuda_runtime.h>
#include <cstdint>
#include <math.h>

#define T_TOK 2048
#define S_C   512
#define L_X   1536
#define DIM   1024
#define NH    16
#define HD    64
#define FFD   4096

// ---------------- static scratch (no allocations allowed) ----------------
__device__ float g_ln  [T_TOK * DIM];
__device__ float g_qkv [T_TOK * 3 * DIM];     // cols: q[0,1024) k[1024,2048) v[2048,3072)
__device__ float g_q   [T_TOK * DIM];
__device__ float g_k   [T_TOK * DIM];
__device__ float g_y   [T_TOK * DIM];
__device__ float g_x1  [T_TOK * DIM];
__device__ float g_ln2 [T_TOK * DIM];
__device__ float g_ff1 [T_TOK * FFD];
__device__ float g_ff3 [T_TOK * FFD];
__device__ float g_part[2 * T_TOK * DIM];     // split-K partials

// ---------------- small helpers ----------------
__device__ __forceinline__ uint32_t f2tf(float x) {
    uint32_t r;
    asm("cvt.rna.tf32.f32 %0, %1;" : "=r"(r) : "f"(x));
    return r;
}

__device__ __forceinline__ void mma_tf32(float* c, const uint32_t* a, const uint32_t* b) {
    asm volatile(
        "mma.sync.aligned.m16n8k8.row.col.f32.tf32.tf32.f32 "
        "{%0,%1,%2,%3}, {%4,%5,%6,%7}, {%8,%9}, {%0,%1,%2,%3};\n"
        : "+f"(c[0]), "+f"(c[1]), "+f"(c[2]), "+f"(c[3])
        : "r"(a[0]), "r"(a[1]), "r"(a[2]), "r"(a[3]), "r"(b[0]), "r"(b[1]));
}

__device__ __forceinline__ void cp16(void* s, const void* g) {
    uint32_t sa = (uint32_t)__cvta_generic_to_shared(s);
    asm volatile("cp.async.cg.shared.global [%0], [%1], 16;\n" :: "r"(sa), "l"(g));
}

// GEMM region table: m-region (c vs x stream) x n-region (two weight sets).
struct GR {
    const float* W[2][2];
    const float* bias[2][2];
    const float* res[2];
    float* C[2][2];
};

// ---------------- LayerNorm over concat([c, x]) rows ----------------
__global__ void ln_concat(const float* __restrict__ x, const float* __restrict__ c,
                          float* __restrict__ out) {
    int row = blockIdx.x;
    const float* src = (row < S_C) ? (c + (size_t)row * DIM)
                                   : (x + (size_t)(row - S_C) * DIM);
    float* dst = out + (size_t)row * DIM;
    __shared__ float red[256];
    int tid = threadIdx.x;

    float4 v = ((const float4*)src)[tid];
    red[tid] = v.x + v.y + v.z + v.w; __syncthreads();
    for (int o = 128; o > 0; o >>= 1) { if (tid < o) red[tid] += red[tid + o]; __syncthreads(); }
    float mean = red[0] * (1.0f / DIM);
    __syncthreads();

    float dx = v.x - mean, dy = v.y - mean, dz = v.z - mean, dw = v.w - mean;
    red[tid] = dx*dx + dy*dy + dz*dz + dw*dw; __syncthreads();
    for (int o = 128; o > 0; o >>= 1) { if (tid < o) red[tid] += red[tid + o]; __syncthreads(); }
    float inv = rsqrtf(red[0] * (1.0f / DIM) + 1e-6f);

    ((float4*)dst)[tid] = make_float4(dx * inv, dy * inv, dz * inv, dw * inv);
}

__global__ void ln_rows(const float* __restrict__ in, float* __restrict__ out) {
    int row = blockIdx.x;
    const float* src = in + (size_t)row * DIM;
    float* dst = out + (size_t)row * DIM;
    __shared__ float red[256];
    int tid = threadIdx.x;

    float4 v = ((const float4*)src)[tid];
    red[tid] = v.x + v.y + v.z + v.w; __syncthreads();
    for (int o = 128; o > 0; o >>= 1) { if (tid < o) red[tid] += red[tid + o]; __syncthreads(); }
    float mean = red[0] * (1.0f / DIM);
    __syncthreads();

    float dx = v.x - mean, dy = v.y - mean, dz = v.z - mean, dw = v.w - mean;
    red[tid] = dx*dx + dy*dy + dz*dz + dw*dw; __syncthreads();
    for (int o = 128; o > 0; o >>= 1) { if (tid < o) red[tid] += red[tid + o]; __syncthreads(); }
    float inv = rsqrtf(red[0] * (1.0f / DIM) + 1e-6f);

    ((float4*)dst)[tid] = make_float4(dx * inv, dy * inv, dz * inv, dw * inv);
}

// ---------------- tf32 tensor-core GEMM, region-fused, optional split-K -------
#define SPLIT_MT (S_C / 128)
__global__ void __launch_bounds__(256, 2) gemm_tf32(
        const float* __restrict__ A, int lda,
        GR g, int nsplit, int ldres, int ldc, int K, int ksplit,
        float* __restrict__ part) {
    extern __shared__ float sm[];
    const int ASZ = 128 * 36;
    float* bufA[2] = { sm,       sm + 2 * ASZ };
    float* bufB[2] = { sm + ASZ, sm + 3 * ASZ };

    int tid = threadIdx.x;
    int mt0 = blockIdx.y, nt0 = blockIdx.x;
    int mr = (mt0 < SPLIT_MT) ? 0 : 1;
    int nr = (nt0 < nsplit) ? 0 : 1;
    int m0 = mt0 * 128;
    int mloc0 = m0 - (mr ? S_C : 0);
    int nloc0 = (nt0 - (nr ? nsplit : 0)) * 128;
    const float* W = g.W[mr][nr];

    int KT = K / 32;
    int KTz = KT / ksplit;
    int kbase = blockIdx.z * KTz * 32;
    const float* AP = A + kbase;
    const float* WP = W + kbase;

    int wid = tid >> 5, lane = tid & 31;
    int wm = (wid >> 2) * 64;
    int wn = (wid & 3) * 32;
    int lr = lane >> 2;
    int lc = lane & 3;

    float acc[4][4][4];
    #pragma unroll
    for (int i = 0; i < 4; i++)
        #pragma unroll
        for (int j = 0; j < 4; j++)
            #pragma unroll
            for (int r = 0; r < 4; r++) acc[i][j][r] = 0.0f;

    {
        #pragma unroll
        for (int i = 0; i < 4; i++) {
            int f = tid + i * 256;
            int row = f >> 3, c4 = (f & 7) * 4;
            cp16(bufA[0] + row * 36 + c4, AP + (size_t)(m0 + row) * lda + c4);
            cp16(bufB[0] + row * 36 + c4, WP + (size_t)(nloc0 + row) * K + c4);
        }
        asm volatile("cp.async.commit_group;\n");
    }

    for (int kt = 0; kt < KTz; kt++) {
        if (kt + 1 < KTz) {
            int k0 = (kt + 1) * 32;
            int b = (kt + 1) & 1;
            #pragma unroll
            for (int i = 0; i < 4; i++) {
                int f = tid + i * 256;
                int row = f >> 3, c4 = (f & 7) * 4;
                cp16(bufA[b] + row * 36 + c4, AP + (size_t)(m0 + row) * lda + k0 + c4);
                cp16(bufB[b] + row * 36 + c4, WP + (size_t)(nloc0 + row) * K + k0 + c4);
            }
            asm volatile("cp.async.commit_group;\n");
            asm volatile("cp.async.wait_group 1;\n");
        } else {
            asm volatile("cp.async.wait_group 0;\n");
        }
        __syncthreads();

        const float* As = bufA[kt & 1];
        const float* Bs = bufB[kt & 1];
        #pragma unroll
        for (int k8 = 0; k8 < 32; k8 += 8) {
            uint32_t af[4][4], bf[4][2];
            #pragma unroll
            for (int mt = 0; mt < 4; mt++) {
                int mb = wm + mt * 16;
                af[mt][0] = f2tf(As[(mb + lr)     * 36 + k8 + lc]);
                af[mt][1] = f2tf(As[(mb + lr + 8) * 36 + k8 + lc]);
                af[mt][2] = f2tf(As[(mb + lr)     * 36 + k8 + lc + 4]);
                af[mt][3] = f2tf(As[(mb + lr + 8) * 36 + k8 + lc + 4]);
            }
            #pragma unroll
            for (int nt = 0; nt < 4; nt++) {
                int nb = wn + nt * 8;
                bf[nt][0] = f2tf(Bs[(nb + lr) * 36 + k8 + lc]);
                bf[nt][1] = f2tf(Bs[(nb + lr) * 36 + k8 + lc + 4]);
            }
            #pragma unroll
            for (int mt = 0; mt < 4; mt++)
                #pragma unroll
                for (int nt = 0; nt < 4; nt++)
                    mma_tf32(acc[mt][nt], af[mt], bf[nt]);
        }
        __syncthreads();
    }

    if (part) {
        float* P = part + ((size_t)blockIdx.z * T_TOK + m0) * DIM;
        #pragma unroll
        for (int mt = 0; mt < 4; mt++)
            #pragma unroll
            for (int nt = 0; nt < 4; nt++) {
                int n = nloc0 + wn + nt * 8 + lc * 2;
                #pragma unroll
                for (int half = 0; half < 2; half++) {
                    int m = wm + mt * 16 + lr + half * 8;
                    *(float2*)(P + (size_t)m * DIM + n) =
                        make_float2(acc[mt][nt][half * 2 + 0], acc[mt][nt][half * 2 + 1]);
                }
            }
        return;
    }

    const float* bias = g.bias[mr][nr];
    const float* res  = g.res[mr];
    float* C = g.C[mr][nr];
    #pragma unroll
    for (int mt = 0; mt < 4; mt++) {
        #pragma unroll
        for (int nt = 0; nt < 4; nt++) {
            int n = nloc0 + wn + nt * 8 + lc * 2;
            float b0 = 0.0f, b1 = 0.0f;
            if (bias) { b0 = bias[n]; b1 = bias[n + 1]; }
            #pragma unroll
            for (int half = 0; half < 2; half++) {
                int m = mloc0 + wm + mt * 16 + lr + half * 8;
                float v0 = acc[mt][nt][half * 2 + 0] + b0;
                float v1 = acc[mt][nt][half * 2 + 1] + b1;
                if (res) {
                    float2 rr = *(const float2*)(res + (size_t)m * ldres + n);
                    v0 += rr.x; v1 += rr.y;
                }
                *(float2*)(C + (size_t)m * ldc + n) = make_float2(v0, v1);
            }
        }
    }
}

// ---------------- split-K=2 reduce ----------------
__global__ void reduce_split2(const float* __restrict__ part,
        const float* __restrict__ b0, const float* __restrict__ b1,
        const float* __restrict__ r0, const float* __restrict__ r1,
        float* __restrict__ C0, float* __restrict__ C1) {
    int row = blockIdx.x;
    int col = threadIdx.x * 4;
    float4 p = *(const float4*)(part + (size_t)row * DIM + col);
    float4 q = *(const float4*)(part + (size_t)(T_TOK + row) * DIM + col);
    const float* bias; const float* res; float* C; int lr_;
    if (row < S_C) { bias = b0; res = r0; C = C0; lr_ = row; }
    else           { bias = b1; res = r1; C = C1; lr_ = row - S_C; }
    float4 bb = *(const float4*)(bias + col);
    float4 rr = *(const float4*)(res + (size_t)lr_ * DIM + col);
    float4 o;
    o.x = p.x + q.x + bb.x + rr.x;
    o.y = p.y + q.y + bb.y + rr.y;
    o.z = p.z + q.z + bb.z + rr.z;
    o.w = p.w + q.w + bb.w + rr.w;
    *(float4*)(C + (size_t)lr_ * DIM + col) = o;
}

// ---------------- per-head RMSNorm + RoPE on q,k (from packed qkv) ------------
__global__ void rmsrope(const float* __restrict__ qkv, const float* __restrict__ freqs,
                        const float* __restrict__ px_qn, const float* __restrict__ px_kn,
                        const float* __restrict__ pc_qn, const float* __restrict__ pc_kn,
                        float* __restrict__ q, float* __restrict__ k) {
    int t = blockIdx.x;
    int h = blockIdx.y * 4 + threadIdx.y;
    int lane = threadIdx.x;

    const float* qn = (t < S_C) ? pc_qn : px_qn;
    const float* kn = (t < S_C) ? pc_kn : px_kn;

    const float* src = qkv + (size_t)t * (3 * DIM) + h * HD;
    float2 qv = *(const float2*)(src + lane * 2);
    float2 kv = *(const float2*)(src + DIM + lane * 2);

    float qs = qv.x * qv.x + qv.y * qv.y;
    float ks = kv.x * kv.x + kv.y * kv.y;
    #pragma unroll
    for (int o = 16; o > 0; o >>= 1) {
        qs += __shfl_xor_sync(0xFFFFFFFFu, qs, o);
        ks += __shfl_xor_sync(0xFFFFFFFFu, ks, o);
    }
    float qinv = rsqrtf(qs * (1.0f / HD) + 1e-6f);
    float kinv = rsqrtf(ks * (1.0f / HD) + 1e-6f);

    float cosv = freqs[((size_t)t * 32 + lane) * 2 + 0];
    float sinv = freqs[((size_t)t * 32 + lane) * 2 + 1];

    float q0 = qv.x * qinv * qn[lane * 2 + 0];
    float q1 = qv.y * qinv * qn[lane * 2 + 1];
    float k0 = kv.x * kinv * kn[lane * 2 + 0];
    float k1 = kv.y * kinv * kn[lane * 2 + 1];

    size_t base = (size_t)t * DIM + h * HD + lane * 2;
    q[base + 0] = q0 * cosv - q1 * sinv;
    q[base + 1] = q0 * sinv + q1 * cosv;
    k[base + 0] = k0 * cosv - k1 * sinv;
    k[base + 1] = k0 * sinv + k1 * cosv;
}

// ---------------- tensor-core causal attention (flash-style, tf32 mma) --------
// 128 threads = 4 warps; warp w owns q-rows [w*16, w*16+16) of a 64-row tile.
// Ks [j][d] stride 68 (b-frag banks 4r+lc, conflict-free), Vs [j][d] stride 72
// (b-frag banks 8*lc+lr, conflict-free), Ps [q][j] stride 68 (warp-private rows).
#define KST 68
#define VST 72
__global__ void __launch_bounds__(128, 3) attn_mma(
        const float* __restrict__ q, const float* __restrict__ k,
        const float* __restrict__ v, int vld, float* __restrict__ y) {
    extern __shared__ float sm[];
    float* Ks = sm;                            // [64][KST]
    float* Vs = sm + 64 * KST;                 // [64][VST]
    float* Ps = sm + 64 * KST + 64 * VST;      // [64][KST]
    float* Qs = Ps;                            // staging overlap (used pre-loop)

    int h = blockIdx.y;
    int qt = gridDim.x - 1 - blockIdx.x;       // heavy q-tiles first
    int q0 = qt * 64;
    int tid = threadIdx.x, wid = tid >> 5, lane = tid & 31;
    int lr = lane >> 2, lc = lane & 3;
    int wq0 = wid * 16;

    // stage Q (pre-scaled by 1/sqrt(64), tf32) then hoist fragments to regs
    for (int f = tid; f < 1024; f += 128) {
        int r = f >> 4, d4 = (f & 15) * 4;
        float4 val = *(const float4*)(q + (size_t)(q0 + r) * DIM + h * HD + d4);
        Qs[r * KST + d4 + 0] = __uint_as_float(f2tf(val.x * 0.125f));
        Qs[r * KST + d4 + 1] = __uint_as_float(f2tf(val.y * 0.125f));
        Qs[r * KST + d4 + 2] = __uint_as_float(f2tf(val.z * 0.125f));
        Qs[r * KST + d4 + 3] = __uint_as_float(f2tf(val.w * 0.125f));
    }
    __syncthreads();
    uint32_t qf[8][4];
    #pragma unroll
    for (int k8 = 0; k8 < 8; k8++) {
        qf[k8][0] = __float_as_uint(Qs[(wq0 + lr)     * KST + k8 * 8 + lc]);
        qf[k8][1] = __float_as_uint(Qs[(wq0 + lr + 8) * KST + k8 * 8 + lc]);
        qf[k8][2] = __float_as_uint(Qs[(wq0 + lr)     * KST + k8 * 8 + lc + 4]);
        qf[k8][3] = __float_as_uint(Qs[(wq0 + lr + 8) * KST + k8 * 8 + lc + 4]);
    }

    float m0 = -1e30f, m1 = -1e30f, l0 = 0.0f, l1 = 0.0f;
    float of[8][4];
    #pragma unroll
    for (int nt = 0; nt < 8; nt++)
        #pragma unroll
        for (int e = 0; e < 4; e++) of[nt][e] = 0.0f;

    for (int kt = 0; kt <= qt; kt++) {
        int j0 = kt * 64;
        __syncthreads();   // prior PV reads of Ks/Vs complete
        for (int f = tid; f < 1024; f += 128) {
            int r = f >> 4, d4 = (f & 15) * 4;
            float4 kk = *(const float4*)(k + (size_t)(j0 + r) * DIM + h * HD + d4);
            float4 kt4;
            kt4.x = __uint_as_float(f2tf(kk.x));
            kt4.y = __uint_as_float(f2tf(kk.y));
            kt4.z = __uint_as_float(f2tf(kk.z));
            kt4.w = __uint_as_float(f2tf(kk.w));
            *(float4*)(Ks + r * KST + d4) = kt4;
            float4 vv = *(const float4*)(v + (size_t)(j0 + r) * vld + h * HD + d4);
            float4 vt4;
            vt4.x = __uint_as_float(f2tf(vv.x));
            vt4.y = __uint_as_float(f2tf(vv.y));
            vt4.z = __uint_as_float(f2tf(vv.z));
            vt4.w = __uint_as_float(f2tf(vv.w));
            *(float4*)(Vs + r * VST + d4) = vt4;
        }
        __syncthreads();

        // S = Q K^T  (8 n-tiles of 8 cols)
        float sf[8][4];
        #pragma unroll
        for (int nt = 0; nt < 8; nt++)
            #pragma unroll
            for (int e = 0; e < 4; e++) sf[nt][e] = 0.0f;
        #pragma unroll
        for (int k8 = 0; k8 < 8; k8++) {
            #pragma unroll
            for (int nt = 0; nt < 8; nt++) {
                uint32_t b[2];
                b[0] = __float_as_uint(Ks[(nt * 8 + lr) * KST + k8 * 8 + lc]);
                b[1] = __float_as_uint(Ks[(nt * 8 + lr) * KST + k8 * 8 + lc + 4]);
                mma_tf32(sf[nt], qf[k8], b);
            }
        }

        // causal mask on diagonal tile (local cols vs local rows)
        if (kt == qt) {
            int r0 = wq0 + lr, r1 = r0 + 8;
            #pragma unroll
            for (int nt = 0; nt < 8; nt++) {
                int col = nt * 8 + lc * 2;
                if (col     > r0) sf[nt][0] = -1e30f;
                if (col + 1 > r0) sf[nt][1] = -1e30f;
                if (col     > r1) sf[nt][2] = -1e30f;
                if (col + 1 > r1) sf[nt][3] = -1e30f;
            }
        }

        // online softmax: rows r0 (c0,c1), r1 (c2,c3); quad = lanes sharing lane/4
        float mx0 = -1e30f, mx1 = -1e30f;
        #pragma unroll
        for (int nt = 0; nt < 8; nt++) {
            mx0 = fmaxf(mx0, fmaxf(sf[nt][0], sf[nt][1]));
            mx1 = fmaxf(mx1, fmaxf(sf[nt][2], sf[nt][3]));
        }
        mx0 = fmaxf(mx0, __shfl_xor_sync(0xFFFFFFFFu, mx0, 1));
        mx0 = fmaxf(mx0, __shfl_xor_sync(0xFFFFFFFFu, mx0, 2));
        mx1 = fmaxf(mx1, __shfl_xor_sync(0xFFFFFFFFu, mx1, 1));
        mx1 = fmaxf(mx1, __shfl_xor_sync(0xFFFFFFFFu, mx1, 2));
        float nm0 = fmaxf(m0, mx0), nm1 = fmaxf(m1, mx1);
        float f0 = __expf(m0 - nm0), f1 = __expf(m1 - nm1);
        float rs0 = 0.0f, rs1 = 0.0f;
        #pragma unroll
        for (int nt = 0; nt < 8; nt++) {
            sf[nt][0] = __expf(sf[nt][0] - nm0); rs0 += sf[nt][0];
            sf[nt][1] = __expf(sf[nt][1] - nm0); rs0 += sf[nt][1];
            sf[nt][2] = __expf(sf[nt][2] - nm1); rs1 += sf[nt][2];
            sf[nt][3] = __expf(sf[nt][3] - nm1); rs1 += sf[nt][3];
        }
        rs0 += __shfl_xor_sync(0xFFFFFFFFu, rs0, 1);
        rs0 += __shfl_xor_sync(0xFFFFFFFFu, rs0, 2);
        rs1 += __shfl_xor_sync(0xFFFFFFFFu, rs1, 1);
        rs1 += __shfl_xor_sync(0xFFFFFFFFu, rs1, 2);
        l0 = l0 * f0 + rs0; l1 = l1 * f1 + rs1;
        m0 = nm0; m1 = nm1;
        #pragma unroll
        for (int nt = 0; nt < 8; nt++) {
            of[nt][0] *= f0; of[nt][1] *= f0;
            of[nt][2] *= f1; of[nt][3] *= f1;
        }

        // P -> warp-private smem rows (tf32), then PV mma
        #pragma unroll
        for (int nt = 0; nt < 8; nt++) {
            int cb = nt * 8 + lc * 2;
            Ps[(wq0 + lr)     * KST + cb + 0] = __uint_as_float(f2tf(sf[nt][0]));
            Ps[(wq0 + lr)     * KST + cb + 1] = __uint_as_float(f2tf(sf[nt][1]));
            Ps[(wq0 + lr + 8) * KST + cb + 0] = __uint_as_float(f2tf(sf[nt][2]));
            Ps[(wq0 + lr + 8) * KST + cb + 1] = __uint_as_float(f2tf(sf[nt][3]));
        }
        __syncwarp();
        #pragma unroll
        for (int k8 = 0; k8 < 8; k8++) {
            uint32_t af[4];
            af[0] = __float_as_uint(Ps[(wq0 + lr)     * KST + k8 * 8 + lc]);
            af[1] = __float_as_uint(Ps[(wq0 + lr + 8) * KST + k8 * 8 + lc]);
            af[2] = __float_as_uint(Ps[(wq0 + lr)     * KST + k8 * 8 + lc + 4]);
            af[3] = __float_as_uint(Ps[(wq0 + lr + 8) * KST + k8 * 8 + lc + 4]);
            #pragma unroll
            for (int nt = 0; nt < 8; nt++) {
                uint32_t b[2];
                b[0] = __float_as_uint(Vs[(k8 * 8 + lc)     * VST + nt * 8 + lr]);
                b[1] = __float_as_uint(Vs[(k8 * 8 + lc + 4) * VST + nt * 8 + lr]);
                mma_tf32(of[nt], af, b);
            }
        }
        __syncwarp();   // Ps reads done before next-iteration overwrite
    }

    float i0 = 1.0f / l0, i1 = 1.0f / l1;
    #pragma unroll
    for (int nt = 0; nt < 8; nt++) {
        int cb = h * HD + nt * 8 + lc * 2;
        *(float2*)(y + (size_t)(q0 + wq0 + lr) * DIM + cb) =
            make_float2(of[nt][0] * i0, of[nt][1] * i0);
        *(float2*)(y + (size_t)(q0 + wq0 + lr + 8) * DIM + cb) =
            make_float2(of[nt][2] * i1, of[nt][3] * i1);
    }
}

// ---------------- SwiGLU gate: a = silu(a) * b ----------------
__global__ void silu_mul(float* __restrict__ a, const float* __restrict__ b, int n4) {
    int i = blockIdx.x * blockDim.x + threadIdx.x;
    if (i < n4) {
        float4 av = ((float4*)a)[i];
        float4 bv = ((const float4*)b)[i];
        av.x = av.x / (1.0f + __expf(-av.x)) * bv.x;
        av.y = av.y / (1.0f + __expf(-av.y)) * bv.y;
        av.z = av.z / (1.0f + __expf(-av.z)) * bv.z;
        av.w = av.w / (1.0f + __expf(-av.w)) * bv.w;
        ((float4*)a)[i] = av;
    }
}

// ---------------- launch ----------------
#define GEMM_SMEM (4 * 128 * 36 * 4)                       // 73728 B
#define ATTN_SMEM ((64 * KST + 64 * VST + 64 * KST) * 4)   // 53248 B

extern "C" void kernel_launch(void* const* d_in, const int* in_sizes, int n_in,
                              void* d_out, int out_size) {
    const float* x        = (const float*)d_in[0];
    const float* c        = (const float*)d_in[1];
    const float* freqs    = (const float*)d_in[2];
    const float* px_qk_w  = (const float*)d_in[3];
    const float* px_qn    = (const float*)d_in[4];
    const float* px_kn    = (const float*)d_in[5];
    const float* px_v_w   = (const float*)d_in[6];
    const float* px_v_b   = (const float*)d_in[7];
    const float* pc_qk_w  = (const float*)d_in[8];
    const float* pc_qn    = (const float*)d_in[9];
    const float* pc_kn    = (const float*)d_in[10];
    const float* pc_v_w   = (const float*)d_in[11];
    const float* pc_v_b   = (const float*)d_in[12];
    const float* p1_proj_w= (const float*)d_in[13];
    const float* p1_proj_b= (const float*)d_in[14];
    const float* p1_w1    = (const float*)d_in[15];
    const float* p1_b1    = (const float*)d_in[16];
    const float* p1_w3    = (const float*)d_in[17];
    const float* p1_b3    = (const float*)d_in[18];
    const float* p1_w2    = (const float*)d_in[19];
    const float* p1_b2    = (const float*)d_in[20];
    const float* p2_proj_w= (const float*)d_in[21];
    const float* p2_proj_b= (const float*)d_in[22];
    const float* p2_w1    = (const float*)d_in[23];
    const float* p2_b1    = (const float*)d_in[24];
    const float* p2_w3    = (const float*)d_in[25];
    const float* p2_b3    = (const float*)d_in[26];
    const float* p2_w2    = (const float*)d_in[27];
    const float* p2_b2    = (const float*)d_in[28];
    float* out = (float*)d_out;

    float *ln_, *qkv_, *q_, *k_, *y_, *x1_, *ln2_, *ff1_, *ff3_, *part_;
    cudaGetSymbolAddress((void**)&ln_,  g_ln);
    cudaGetSymbolAddress((void**)&qkv_, g_qkv);
    cudaGetSymbolAddress((void**)&q_,   g_q);
    cudaGetSymbolAddress((void**)&k_,   g_k);
    cudaGetSymbolAddress((void**)&y_,   g_y);
    cudaGetSymbolAddress((void**)&x1_,  g_x1);
    cudaGetSymbolAddress((void**)&ln2_, g_ln2);
    cudaGetSymbolAddress((void**)&ff1_, g_ff1);
    cudaGetSymbolAddress((void**)&ff3_, g_ff3);
    cudaGetSymbolAddress((void**)&part_, g_part);

    cudaFuncSetAttribute(gemm_tf32, cudaFuncAttributeMaxDynamicSharedMemorySize, GEMM_SMEM);
    cudaFuncSetAttribute(attn_mma, cudaFuncAttributeMaxDynamicSharedMemorySize, ATTN_SMEM);

    // 1. LN on both streams into unified [c; x] token order
    ln_concat<<<T_TOK, 256>>>(x, c, ln_);

    // 2+3. fused qkv projection: n-tiles 0-15 -> qk weights, 16-23 -> v weights
    {
        GR g = {};
        g.W[0][0] = pc_qk_w;  g.W[0][1] = pc_v_w;
        g.W[1][0] = px_qk_w;  g.W[1][1] = px_v_w;
        g.bias[0][1] = pc_v_b; g.bias[1][1] = px_v_b;
        g.C[0][0] = qkv_;                           g.C[0][1] = qkv_ + 2 * DIM;
        g.C[1][0] = qkv_ + (size_t)S_C * 3 * DIM;   g.C[1][1] = qkv_ + (size_t)S_C * 3 * DIM + 2 * DIM;
        gemm_tf32<<<dim3(24, T_TOK / 128, 1), 256, GEMM_SMEM>>>(
            ln_, DIM, g, 16, 0, 3 * DIM, DIM, 1, nullptr);
    }

    // 4. per-head RMSNorm + RoPE
    rmsrope<<<dim3(T_TOK, NH / 4), dim3(32, 4)>>>(qkv_, freqs, px_qn, px_kn, pc_qn, pc_kn, q_, k_);

    // 5. tensor-core causal attention (v packed in qkv, stride 3072)
    attn_mma<<<dim3(T_TOK / 64, NH), 128, ATTN_SMEM>>>(q_, k_, qkv_ + 2 * DIM, 3 * DIM, y_);

    // 6. output projection, split-K=2 -> partials, then reduce (+bias +res)
    {
        GR g = {};
        g.W[0][0] = p2_proj_w;  g.W[1][0] = p1_proj_w;
        gemm_tf32<<<dim3(DIM / 128, T_TOK / 128, 2), 256, GEMM_SMEM>>>(
            y_, DIM, g, 1000, 0, DIM, DIM, 2, part_);
        reduce_split2<<<T_TOK, 256>>>(part_, p2_proj_b, p1_proj_b, c, x,
                                      x1_, x1_ + (size_t)S_C * DIM);
    }

    // 7. second LN
    ln_rows<<<T_TOK, 256>>>(x1_, ln2_);

    // 8. fused MLP up projection: n-tiles 0-31 -> w1, 32-63 -> w3
    {
        GR g = {};
        g.W[0][0] = p2_w1;  g.W[0][1] = p2_w3;
        g.W[1][0] = p1_w1;  g.W[1][1] = p1_w3;
        g.bias[0][0] = p2_b1; g.bias[0][1] = p2_b3;
        g.bias[1][0] = p1_b1; g.bias[1][1] = p1_b3;
        g.C[0][0] = ff1_;                        g.C[0][1] = ff3_;
        g.C[1][0] = ff1_ + (size_t)S_C * FFD;    g.C[1][1] = ff3_ + (size_t)S_C * FFD;
        gemm_tf32<<<dim3(64, T_TOK / 128, 1), 256, GEMM_SMEM>>>(
            ln2_, DIM, g, 32, 0, FFD, DIM, 1, nullptr);
    }

    // 9. SwiGLU gate
    {
        int n4 = T_TOK * FFD / 4;
        silu_mul<<<(n4 + 255) / 256, 256>>>(ff1_, ff3_, n4);
    }

    // 10. MLP down projection, split-K=2 -> partials, then reduce (+bias +res)
    {
        GR g = {};
        g.W[0][0] = p2_w2;  g.W[1][0] = p1_w2;
        gemm_tf32<<<dim3(DIM / 128, T_TOK / 128, 2), 256, GEMM_SMEM>>>(
            ff1_, FFD, g, 1000, 0, DIM, FFD, 2, part_);
        reduce_split2<<<T_TOK, 256>>>(part_, p2_b2, p1_b2, x1_, x1_ + (size_t)S_C * DIM,
                                      out + (size_t)L_X * DIM, out);
    }
}